// round 10
// baseline (speedup 1.0000x reference)
#include <cuda_runtime.h>
#include <cstdint>

#define NBLK   148
#define TPB_E  512
#define TILE16 (16*132)                           // 2112 floats per 16-row tile
#define WB_FLOATS (8*16*32*4)                     // 16384 floats = 64 KB (W frag layout)
#define MMA_SMEM ((WB_FLOATS + 16*TILE16) * 4)    // 64KB + 132KB = 200704 B

// Scratch (device globals: allocation-free rule)
__device__ float g_A   [50000 * 128];
__device__ float g_B   [50000 * 128];
__device__ float g_agg [50000 * 128];
__device__ float g_pool[64 * 128];
__device__ float g_cnt [64];
__device__ int   g_deg [50000];
__device__ int   g_start[50001];
__device__ int   g_cursor[50000];
__device__ int   g_ssrc[800000];
__device__ float g_wfrag[6 * 16384];              // w1t/w1b frag buffers, 3 layers

__device__ __forceinline__ float4 relu4(float4 v) {
    v.x = fmaxf(v.x, 0.f); v.y = fmaxf(v.y, 0.f);
    v.z = fmaxf(v.z, 0.f); v.w = fmaxf(v.w, 0.f);
    return v;
}

// ======================= tf32 mma helpers =======================
__device__ __forceinline__ uint32_t f2tf32(float f) {
    uint32_t r; asm("cvt.rna.tf32.f32 %0, %1;" : "=r"(r) : "f"(f)); return r;
}
__device__ __forceinline__ void mma8(float4 &d, const uint32_t a[4],
                                     uint32_t b0, uint32_t b1) {
    asm volatile("mma.sync.aligned.m16n8k8.row.col.f32.tf32.tf32.f32 "
        "{%0,%1,%2,%3}, {%4,%5,%6,%7}, {%8,%9}, {%0,%1,%2,%3};"
        : "+f"(d.x), "+f"(d.y), "+f"(d.z), "+f"(d.w)
        : "r"(a[0]), "r"(a[1]), "r"(a[2]), "r"(a[3]), "r"(b0), "r"(b1));
}
__device__ __forceinline__ void split4hl(float4 v, uint32_t h[4], uint32_t l[4]) {
    h[0] = f2tf32(v.x); l[0] = f2tf32(v.x - __uint_as_float(h[0]));
    h[1] = f2tf32(v.y); l[1] = f2tf32(v.y - __uint_as_float(h[1]));
    h[2] = f2tf32(v.z); l[2] = f2tf32(v.z - __uint_as_float(h[2]));
    h[3] = f2tf32(v.w); l[3] = f2tf32(v.w - __uint_as_float(h[3]));
}

// W (row-major [k][n], 128x128) -> B-fragment uint4 at index i (0..4095)
__device__ __forceinline__ uint4 wfrag_entry(const float* __restrict__ W, int i) {
    int kk2 = i >> 9, rem = i & 511, nb = rem >> 5, ln = rem & 31;
    int n = nb * 8 + (ln >> 2), k = kk2 * 16 + (ln & 3);
    uint4 v;
    v.x = f2tf32(W[(k     ) * 128 + n]);
    v.y = f2tf32(W[(k +  4) * 128 + n]);
    v.z = f2tf32(W[(k +  8) * 128 + n]);
    v.w = f2tf32(W[(k + 12) * 128 + n]);
    return v;
}
__device__ __forceinline__ void stage_w_frag(float* Wb, const float* __restrict__ W) {
    for (int i = threadIdx.x; i < 4096; i += TPB_E)
        ((uint4*)Wb)[i] = wfrag_entry(W, i);
}

// tile address of element (row e 0..15, col c 0..127)
__device__ __forceinline__ int faddr(int e, int c) {
    return (c >> 3) * 132 + ((c >> 2) & 1) * 2 + (c & 3) * 4 + (e & 7) * 16 + (e >> 3);
}

// m16 x n128 x k128 mainloop over the tile, hi/lo compensated activations.
__device__ __forceinline__ void mma_mainloop(float4 acc[16], const float* ta,
                                             const uint4* __restrict__ wf, int lane) {
    #pragma unroll
    for (int nb = 0; nb < 16; nb++) acc[nb] = make_float4(0.f, 0.f, 0.f, 0.f);
    #pragma unroll
    for (int kk2 = 0; kk2 < 8; kk2++) {
        float4 ve = *(const float4*)(ta + (2 * kk2    ) * 132 + lane * 4);
        float4 vo = *(const float4*)(ta + (2 * kk2 + 1) * 132 + lane * 4);
        uint32_t he[4], le[4], ho[4], lo[4];
        split4hl(ve, he, le);
        split4hl(vo, ho, lo);
        const uint4* wrow = wf + kk2 * 512 + lane;
        #pragma unroll
        for (int nb = 0; nb < 16; nb++) {
            uint4 B = wrow[nb * 32];
            mma8(acc[nb], he, B.x, B.y);
            mma8(acc[nb], le, B.x, B.y);
            mma8(acc[nb], ho, B.z, B.w);
            mma8(acc[nb], lo, B.z, B.w);
        }
    }
}

__device__ __forceinline__ void redv2(float* p, float a, float b) {
    asm volatile("red.global.add.v2.f32 [%0], {%1, %2};" :: "l"(p), "f"(a), "f"(b) : "memory");
}

// ======================= LAB kernel: lin + A + B fused =======================
// h = (RELU_IN ? relu(X) : X) @ lin_w + lin_b   (kept in smem tile only)
// A = h @ w1t + b1 ; B = h @ w1b               (w1t/w1b from global frag buffers)
template <bool RELU_IN>
__global__ void __launch_bounds__(TPB_E, 1)
lab_kernel(const float* __restrict__ X, const float* __restrict__ Wlin,
           const float* __restrict__ linb, const float* __restrict__ w1t_f,
           const float* __restrict__ w1b_f, const float* __restrict__ b1,
           float* __restrict__ Aout, float* __restrict__ Bout, int nrows)
{
    extern __shared__ float sm[];
    float* Wb = sm;
    const int tid = threadIdx.x, wid = tid >> 5, lane = tid & 31;
    float* ta = sm + WB_FLOATS + wid * TILE16;

    stage_w_frag(Wb, Wlin);
    __syncthreads();

    const int gwarp  = blockIdx.x * 16 + wid;
    const int nwarps = gridDim.x * 16;
    const int ntasks = (nrows + 15) / 16;
    const int sbase  = (lane >> 1) * 132 + 2 * (lane & 1);

    for (int task = gwarp; task < ntasks; task += nwarps) {
        const int r0 = task * 16;

        // ---- gather X ----
        #pragma unroll 4
        for (int e = 0; e < 16; e++) {
            int r = r0 + e;
            float4 t = make_float4(0.f, 0.f, 0.f, 0.f);
            if (r < nrows) {
                t = ((const float4*)(X + (size_t)r * 128))[lane];
                if (RELU_IN) t = relu4(t);
            }
            float* p = ta + sbase + (e & 7) * 16 + (e >> 3);
            p[0] = t.x; p[4] = t.y; p[8] = t.z; p[12] = t.w;
        }
        __syncwarp();

        float4 acc[16];
        const int e0 = lane >> 2;
        const int i0 = r0 + e0, i1 = i0 + 8;

        // ---- MMA1: h = X @ Wlin (smem W) ----
        mma_mainloop(acc, ta, (const uint4*)Wb, lane);
        __syncwarp();
        // writeback h (+ lin bias) into the same tile
        #pragma unroll
        for (int nb = 0; nb < 16; nb++) {
            int c = 2 * (lane & 3) + nb * 8;
            float q0 = __ldg(linb + c), q1 = __ldg(linb + c + 1);
            ta[faddr(e0,     c)]     = acc[nb].x + q0;
            ta[faddr(e0,     c + 1)] = acc[nb].y + q1;
            ta[faddr(e0 + 8, c)]     = acc[nb].z + q0;
            ta[faddr(e0 + 8, c + 1)] = acc[nb].w + q1;
        }
        __syncwarp();

        // ---- MMA2: A = h @ w1t + b1 ----
        mma_mainloop(acc, ta, (const uint4*)w1t_f, lane);
        #pragma unroll
        for (int nb = 0; nb < 16; nb++) {
            int c = 2 * (lane & 3) + nb * 8;
            float q0 = __ldg(b1 + c), q1 = __ldg(b1 + c + 1);
            if (i0 < nrows)
                *(float2*)(Aout + (size_t)i0 * 128 + c) = make_float2(acc[nb].x + q0, acc[nb].y + q1);
            if (i1 < nrows)
                *(float2*)(Aout + (size_t)i1 * 128 + c) = make_float2(acc[nb].z + q0, acc[nb].w + q1);
        }

        // ---- MMA3: B = h @ w1b ----
        mma_mainloop(acc, ta, (const uint4*)w1b_f, lane);
        #pragma unroll
        for (int nb = 0; nb < 16; nb++) {
            int c = 2 * (lane & 3) + nb * 8;
            if (i0 < nrows)
                *(float2*)(Bout + (size_t)i0 * 128 + c) = make_float2(acc[nb].x, acc[nb].y);
            if (i1 < nrows)
                *(float2*)(Bout + (size_t)i1 * 128 + c) = make_float2(acc[nb].z, acc[nb].w);
        }
        __syncwarp();
    }
}

// ======================= accum + msg GEMM fused =======================
// T[n] = relu(A[n]+B[n]) + sum_{e in CSR[n]} relu(A[n]+B[ssrc[e]])  (smem tile only)
// out  = T @ w2 + (deg+1)*b2 ;  POOL: relu + pool atomics, else store agg.
template <bool POOL>
__global__ void __launch_bounds__(TPB_E, 1)
accum_msg_kernel(const float* __restrict__ A, const float* __restrict__ B,
                 const int* __restrict__ ssrc, const int* __restrict__ start,
                 const float* __restrict__ W2, const float* __restrict__ b2,
                 const int* __restrict__ deg, const int* __restrict__ batch,
                 float* __restrict__ agg, float* __restrict__ pool, int nrows)
{
    extern __shared__ float sm[];
    float* Wb = sm;
    const int tid = threadIdx.x, wid = tid >> 5, lane = tid & 31;
    float* ta = sm + WB_FLOATS + wid * TILE16;

    stage_w_frag(Wb, W2);
    __syncthreads();

    const int gwarp  = blockIdx.x * 16 + wid;
    const int nwarps = gridDim.x * 16;
    const int ntasks = (nrows + 15) / 16;
    const int sbase  = (lane >> 1) * 132 + 2 * (lane & 1);

    for (int task = gwarp; task < ntasks; task += nwarps) {
        const int r0 = task * 16;

        // ---- phase 1: accumulate relu'd messages per node, write tile ----
        for (int e = 0; e < 16; e++) {
            int node = r0 + e;
            float4 acc4 = make_float4(0.f, 0.f, 0.f, 0.f);
            if (node < nrows) {
                float4 a  = ((const float4*)(A + (size_t)node * 128))[lane];
                float4 bs = ((const float4*)(B + (size_t)node * 128))[lane];
                acc4 = relu4(make_float4(a.x + bs.x, a.y + bs.y, a.z + bs.z, a.w + bs.w)); // self loop
                int ei  = __ldg(start + node);
                int ee  = __ldg(start + node + 1);
                for (; ei + 4 <= ee; ei += 4) {
                    int j0 = __ldg(ssrc + ei),     j1 = __ldg(ssrc + ei + 1);
                    int j2 = __ldg(ssrc + ei + 2), j3 = __ldg(ssrc + ei + 3);
                    float4 b0 = ((const float4*)(B + (size_t)j0 * 128))[lane];
                    float4 b1v = ((const float4*)(B + (size_t)j1 * 128))[lane];
                    float4 b2v = ((const float4*)(B + (size_t)j2 * 128))[lane];
                    float4 b3 = ((const float4*)(B + (size_t)j3 * 128))[lane];
                    float4 t0 = relu4(make_float4(a.x + b0.x, a.y + b0.y, a.z + b0.z, a.w + b0.w));
                    float4 t1 = relu4(make_float4(a.x + b1v.x, a.y + b1v.y, a.z + b1v.z, a.w + b1v.w));
                    float4 t2 = relu4(make_float4(a.x + b2v.x, a.y + b2v.y, a.z + b2v.z, a.w + b2v.w));
                    float4 t3 = relu4(make_float4(a.x + b3.x, a.y + b3.y, a.z + b3.z, a.w + b3.w));
                    acc4.x += t0.x + t1.x + t2.x + t3.x;
                    acc4.y += t0.y + t1.y + t2.y + t3.y;
                    acc4.z += t0.z + t1.z + t2.z + t3.z;
                    acc4.w += t0.w + t1.w + t2.w + t3.w;
                }
                for (; ei < ee; ei++) {
                    int j = __ldg(ssrc + ei);
                    float4 b = ((const float4*)(B + (size_t)j * 128))[lane];
                    float4 t = relu4(make_float4(a.x + b.x, a.y + b.y, a.z + b.z, a.w + b.w));
                    acc4.x += t.x; acc4.y += t.y; acc4.z += t.z; acc4.w += t.w;
                }
            }
            float* p = ta + sbase + (e & 7) * 16 + (e >> 3);
            p[0] = acc4.x; p[4] = acc4.y; p[8] = acc4.z; p[12] = acc4.w;
        }
        __syncwarp();

        // ---- phase 2: MMA with w2 ----
        float4 acc[16];
        mma_mainloop(acc, ta, (const uint4*)Wb, lane);
        __syncwarp();

        // ---- epilogue ----
        int i0 = r0 + (lane >> 2);
        int i1 = i0 + 8;
        float s0 = 0.f, s1 = 0.f;
        int g0 = 0, g1 = 0;
        if (i0 < nrows) { s0 = (float)(__ldg(deg + i0) + 1); if (POOL) g0 = __ldg(batch + i0); }
        if (i1 < nrows) { s1 = (float)(__ldg(deg + i1) + 1); if (POOL) g1 = __ldg(batch + i1); }
        #pragma unroll
        for (int nb = 0; nb < 16; nb++) {
            int c = 2 * (lane & 3) + nb * 8;
            float q0 = __ldg(b2 + c), q1 = __ldg(b2 + c + 1);
            if (POOL) {
                if (i0 < nrows)
                    redv2(pool + (size_t)g0 * 128 + c,
                          fmaxf(acc[nb].x + s0 * q0, 0.f), fmaxf(acc[nb].y + s0 * q1, 0.f));
                if (i1 < nrows)
                    redv2(pool + (size_t)g1 * 128 + c,
                          fmaxf(acc[nb].z + s1 * q0, 0.f), fmaxf(acc[nb].w + s1 * q1, 0.f));
            } else {
                if (i0 < nrows)
                    *(float2*)(agg + (size_t)i0 * 128 + c) = make_float2(acc[nb].x + s0 * q0, acc[nb].y + s0 * q1);
                if (i1 < nrows)
                    *(float2*)(agg + (size_t)i1 * 128 + c) = make_float2(acc[nb].z + s1 * q0, acc[nb].w + s1 * q1);
            }
        }
    }
}

// ======================= prep / CSR / final =======================
__global__ void wfrag_kernel(const float* __restrict__ W, float* __restrict__ out) {
    int i = blockIdx.x * blockDim.x + threadIdx.x;
    if (i < 4096) ((uint4*)out)[i] = wfrag_entry(W, i);
}

__global__ void deg_kernel(const int* __restrict__ dst, int* __restrict__ deg, int E) {
    int i = blockIdx.x * blockDim.x + threadIdx.x;
    if (i < E) atomicAdd(&deg[dst[i]], 1);
}

__global__ void cnt_kernel(const int* __restrict__ batch, float* __restrict__ cnt, int n) {
    int i = blockIdx.x * blockDim.x + threadIdx.x;
    if (i < n) atomicAdd(&cnt[batch[i]], 1.f);
}

__global__ void scan_kernel(const int* __restrict__ deg, int* __restrict__ start,
                            int* __restrict__ cursor, int n)
{
    __shared__ int carry;
    __shared__ int wsum[32];
    const int tidx = threadIdx.x, lane = tidx & 31, wid = tidx >> 5;
    if (tidx == 0) carry = 0;
    __syncthreads();

    for (int base = 0; base < n; base += 1024) {
        int i = base + tidx;
        int v = (i < n) ? deg[i] : 0;
        int x = v;
        #pragma unroll
        for (int o = 1; o < 32; o <<= 1) {
            int y = __shfl_up_sync(0xffffffffu, x, o);
            if (lane >= o) x += y;
        }
        if (lane == 31) wsum[wid] = x;
        __syncthreads();
        if (wid == 0) {
            int w = wsum[lane];
            #pragma unroll
            for (int o = 1; o < 32; o <<= 1) {
                int y = __shfl_up_sync(0xffffffffu, w, o);
                if (lane >= o) w += y;
            }
            wsum[lane] = w;
        }
        __syncthreads();
        int excl = x - v + (wid > 0 ? wsum[wid - 1] : 0) + carry;
        if (i < n) { start[i] = excl; cursor[i] = excl; }
        int blocktot = wsum[31];
        __syncthreads();
        if (tidx == 0) carry += blocktot;
        __syncthreads();
    }
    if (tidx == 0) start[n] = carry;
}

__global__ void scatter_kernel(const int* __restrict__ src, const int* __restrict__ dst,
                               int* __restrict__ cursor, int* __restrict__ ssrc, int E)
{
    int i = blockIdx.x * blockDim.x + threadIdx.x;
    if (i < E) {
        int p = atomicAdd(&cursor[dst[i]], 1);
        ssrc[p] = src[i];
    }
}

__global__ void final_kernel(const float* __restrict__ pool, const float* __restrict__ cnt,
                             const float* __restrict__ W, const float* __restrict__ b,
                             float* __restrict__ out)
{
    __shared__ float p[128];
    int g = blockIdx.x;
    float c = fmaxf(cnt[g], 1.f);
    for (int j = threadIdx.x; j < 128; j += blockDim.x)
        p[j] = pool[(size_t)g * 128 + j] / c;
    __syncthreads();
    int o = threadIdx.x;
    float s = b[o];
    #pragma unroll 4
    for (int j = 0; j < 128; j++) s += p[j] * W[j * 64 + o];
    out[(size_t)g * 64 + o] = s;
}

// ======================= launch =======================
extern "C" void kernel_launch(void* const* d_in, const int* in_sizes, int n_in,
                              void* d_out, int out_size)
{
    const float* x     = (const float*)d_in[0];
    const int*   ei    = (const int*)  d_in[1];
    const int*   batch = (const int*)  d_in[3];
    const int N = in_sizes[0] / 128;
    const int E = in_sizes[1] / 2;
    const int* src = ei;
    const int* dst = ei + E;

    const float* lin_w[3] = { (const float*)d_in[4],  (const float*)d_in[10], (const float*)d_in[16] };
    const float* lin_b[3] = { (const float*)d_in[5],  (const float*)d_in[11], (const float*)d_in[17] };
    const float* w1[3]    = { (const float*)d_in[6],  (const float*)d_in[12], (const float*)d_in[18] };
    const float* b1[3]    = { (const float*)d_in[7],  (const float*)d_in[13], (const float*)d_in[19] };
    const float* w2[3]    = { (const float*)d_in[8],  (const float*)d_in[14], (const float*)d_in[20] };
    const float* b2[3]    = { (const float*)d_in[9],  (const float*)d_in[15], (const float*)d_in[21] };
    const float* out_w    = (const float*)d_in[22];
    const float* out_b    = (const float*)d_in[23];
    float* out = (float*)d_out;

    float *A_, *B_, *agg_, *pool_, *cnt_, *wf_;
    int *deg_, *start_, *cursor_, *ssrc_;
    cudaGetSymbolAddress((void**)&A_,     g_A);
    cudaGetSymbolAddress((void**)&B_,     g_B);
    cudaGetSymbolAddress((void**)&agg_,   g_agg);
    cudaGetSymbolAddress((void**)&pool_,  g_pool);
    cudaGetSymbolAddress((void**)&cnt_,   g_cnt);
    cudaGetSymbolAddress((void**)&deg_,   g_deg);
    cudaGetSymbolAddress((void**)&start_, g_start);
    cudaGetSymbolAddress((void**)&cursor_,g_cursor);
    cudaGetSymbolAddress((void**)&ssrc_,  g_ssrc);
    cudaGetSymbolAddress((void**)&wf_,    g_wfrag);

    cudaFuncSetAttribute((const void*)lab_kernel<false>,
                         cudaFuncAttributeMaxDynamicSharedMemorySize, MMA_SMEM);
    cudaFuncSetAttribute((const void*)lab_kernel<true>,
                         cudaFuncAttributeMaxDynamicSharedMemorySize, MMA_SMEM);
    cudaFuncSetAttribute((const void*)accum_msg_kernel<false>,
                         cudaFuncAttributeMaxDynamicSharedMemorySize, MMA_SMEM);
    cudaFuncSetAttribute((const void*)accum_msg_kernel<true>,
                         cudaFuncAttributeMaxDynamicSharedMemorySize, MMA_SMEM);

    const int G = out_size / 64;

    // ---- prep: CSR by dst, graph counts, W1 frag buffers ----
    cudaMemsetAsync(deg_,  0, (size_t)N * sizeof(int));
    cudaMemsetAsync(pool_, 0, (size_t)G * 128 * sizeof(float));
    cudaMemsetAsync(cnt_,  0, (size_t)G * sizeof(float));
    deg_kernel<<<(E + 255) / 256, 256>>>(dst, deg_, E);
    cnt_kernel<<<(N + 255) / 256, 256>>>(batch, cnt_, N);
    scan_kernel<<<1, 1024>>>(deg_, start_, cursor_, N);
    scatter_kernel<<<(E + 255) / 256, 256>>>(src, dst, cursor_, ssrc_, E);
    for (int l = 0; l < 3; l++) {
        wfrag_kernel<<<8, 512>>>(w1[l],             wf_ + (2 * l    ) * 16384);
        wfrag_kernel<<<8, 512>>>(w1[l] + 128 * 128, wf_ + (2 * l + 1) * 16384);
    }

    for (int l = 0; l < 3; l++) {
        const float* X = (l == 0) ? x : agg_;
        const float* w1t_f = wf_ + (2 * l    ) * 16384;
        const float* w1b_f = wf_ + (2 * l + 1) * 16384;
        if (l == 0)
            lab_kernel<false><<<NBLK, TPB_E, MMA_SMEM>>>(X, lin_w[l], lin_b[l], w1t_f, w1b_f, b1[l], A_, B_, N);
        else
            lab_kernel<true ><<<NBLK, TPB_E, MMA_SMEM>>>(X, lin_w[l], lin_b[l], w1t_f, w1b_f, b1[l], A_, B_, N);
        if (l < 2)
            accum_msg_kernel<false><<<NBLK, TPB_E, MMA_SMEM>>>(A_, B_, ssrc_, start_, w2[l], b2[l],
                                                               deg_, batch, agg_, pool_, N);
        else
            accum_msg_kernel<true ><<<NBLK, TPB_E, MMA_SMEM>>>(A_, B_, ssrc_, start_, w2[l], b2[l],
                                                               deg_, batch, agg_, pool_, N);
    }

    final_kernel<<<G, 64>>>(pool_, cnt_, out_w, out_b, out);
}

// round 11
// speedup vs baseline: 1.4875x; 1.4875x over previous
#include <cuda_runtime.h>
#include <cstdint>

#define NBLK_G 98                                  // 98*16 warps * 2 tasks = 3136 >= 3125
#define TPB_E  512
#define TILE16 (16*132)                            // 2112 floats per 16-row tile
#define WB_FLOATS (8*16*32*4)                      // 16384 floats = 64 KB (W frag layout)
#define MMA_SMEM ((WB_FLOATS + 16*TILE16) * 4)     // 64KB + 132KB = 200704 B

// Scratch (device globals: allocation-free rule)
__device__ float g_h   [50000 * 128];
__device__ float g_A   [50000 * 128];
__device__ float g_B   [50000 * 128];
__device__ float g_agg [50000 * 128];
__device__ float g_pool[64 * 128];
__device__ float g_cnt [64];
__device__ int   g_deg [50000];
__device__ int   g_start[50001];
__device__ int   g_cursor[50000];
__device__ int   g_ssrc[800000];

__device__ __forceinline__ float4 relu4(float4 v) {
    v.x = fmaxf(v.x, 0.f); v.y = fmaxf(v.y, 0.f);
    v.z = fmaxf(v.z, 0.f); v.w = fmaxf(v.w, 0.f);
    return v;
}

// ======================= tf32 mma helpers =======================
__device__ __forceinline__ uint32_t f2tf32(float f) {
    uint32_t r; asm("cvt.rna.tf32.f32 %0, %1;" : "=r"(r) : "f"(f)); return r;
}
__device__ __forceinline__ void mma8(float4 &d, const uint32_t a[4],
                                     uint32_t b0, uint32_t b1) {
    asm volatile("mma.sync.aligned.m16n8k8.row.col.f32.tf32.tf32.f32 "
        "{%0,%1,%2,%3}, {%4,%5,%6,%7}, {%8,%9}, {%0,%1,%2,%3};"
        : "+f"(d.x), "+f"(d.y), "+f"(d.z), "+f"(d.w)
        : "r"(a[0]), "r"(a[1]), "r"(a[2]), "r"(a[3]), "r"(b0), "r"(b1));
}
__device__ __forceinline__ void split4hl(float4 v, uint32_t h[4], uint32_t l[4]) {
    h[0] = f2tf32(v.x); l[0] = f2tf32(v.x - __uint_as_float(h[0]));
    h[1] = f2tf32(v.y); l[1] = f2tf32(v.y - __uint_as_float(h[1]));
    h[2] = f2tf32(v.z); l[2] = f2tf32(v.z - __uint_as_float(h[2]));
    h[3] = f2tf32(v.w); l[3] = f2tf32(v.w - __uint_as_float(h[3]));
}

// Stage W (row-major [k][n], 128x128) into B-fragment layout, tf32-rounded.
__device__ __forceinline__ void stage_w_frag(float* Wb, const float* __restrict__ W) {
    for (int i = threadIdx.x; i < 4096; i += TPB_E) {
        int kk2 = i >> 9, rem = i & 511, nb = rem >> 5, ln = rem & 31;
        int n = nb * 8 + (ln >> 2), k = kk2 * 16 + (ln & 3);
        uint4 v;
        v.x = f2tf32(W[(k     ) * 128 + n]);
        v.y = f2tf32(W[(k +  4) * 128 + n]);
        v.z = f2tf32(W[(k +  8) * 128 + n]);
        v.w = f2tf32(W[(k + 12) * 128 + n]);
        ((uint4*)Wb)[i] = v;
    }
}

// m16 x n128 x k128 mainloop over the tile, hi/lo compensated activations.
__device__ __forceinline__ void mma_mainloop(float4 acc[16], const float* ta,
                                             const uint4* wf, int lane) {
    #pragma unroll
    for (int nb = 0; nb < 16; nb++) acc[nb] = make_float4(0.f, 0.f, 0.f, 0.f);
    #pragma unroll
    for (int kk2 = 0; kk2 < 8; kk2++) {
        float4 ve = *(const float4*)(ta + (2 * kk2    ) * 132 + lane * 4);
        float4 vo = *(const float4*)(ta + (2 * kk2 + 1) * 132 + lane * 4);
        uint32_t he[4], le[4], ho[4], lo[4];
        split4hl(ve, he, le);
        split4hl(vo, ho, lo);
        const uint4* wrow = wf + kk2 * 512 + lane;
        #pragma unroll
        for (int nb = 0; nb < 16; nb++) {
            uint4 B = wrow[nb * 32];
            mma8(acc[nb], he, B.x, B.y);
            mma8(acc[nb], le, B.x, B.y);
            mma8(acc[nb], ho, B.z, B.w);
            mma8(acc[nb], lo, B.z, B.w);
        }
    }
}

__device__ __forceinline__ void redv2(float* p, float a, float b) {
    asm volatile("red.global.add.v2.f32 [%0], {%1, %2};" :: "l"(p), "f"(a), "f"(b) : "memory");
}

// ======================= node GEMM: tf32 mma, hi/lo compensated =======================
// Y[r] = (RELU_IN ? relu(X[r]) : X[r]) @ W + bias
template <bool RELU_IN>
__global__ void __launch_bounds__(TPB_E, 1)
node_mma_kernel(const float* __restrict__ X, const float* __restrict__ W,
                const float* __restrict__ bias, float* __restrict__ Y, int nrows)
{
    extern __shared__ float sm[];
    float* Wb = sm;
    const int tid = threadIdx.x, wid = tid >> 5, lane = tid & 31;
    float* ta = sm + WB_FLOATS + wid * TILE16;

    stage_w_frag(Wb, W);
    __syncthreads();

    const int gwarp  = blockIdx.x * 16 + wid;
    const int nwarps = gridDim.x * 16;
    const int ntasks = (nrows + 15) / 16;
    const int sbase  = (lane >> 1) * 132 + 2 * (lane & 1);

    for (int task = gwarp; task < ntasks; task += nwarps) {
        const int r0 = task * 16;

        #pragma unroll 4
        for (int e = 0; e < 16; e++) {
            int r = r0 + e;
            float4 t = make_float4(0.f, 0.f, 0.f, 0.f);
            if (r < nrows) {
                t = ((const float4*)(X + (size_t)r * 128))[lane];
                if (RELU_IN) t = relu4(t);
            }
            float* p = ta + sbase + (e & 7) * 16 + (e >> 3);
            p[0] = t.x; p[4] = t.y; p[8] = t.z; p[12] = t.w;
        }
        __syncwarp();

        float4 acc[16];
        mma_mainloop(acc, ta, (const uint4*)Wb, lane);
        __syncwarp();

        int i0 = r0 + (lane >> 2);
        int i1 = i0 + 8;
        #pragma unroll
        for (int nb = 0; nb < 16; nb++) {
            int c = 2 * (lane & 3) + nb * 8;
            float b0 = 0.f, b1 = 0.f;
            if (bias) { b0 = __ldg(bias + c); b1 = __ldg(bias + c + 1); }
            if (i0 < nrows)
                *(float2*)(Y + (size_t)i0 * 128 + c) = make_float2(acc[nb].x + b0, acc[nb].y + b1);
            if (i1 < nrows)
                *(float2*)(Y + (size_t)i1 * 128 + c) = make_float2(acc[nb].z + b0, acc[nb].w + b1);
        }
    }
}

// ======================= accum + msg GEMM fused (W2 in smem) =======================
// T[n] = relu(A[n]+B[n]) + sum_{e in CSR[n]} relu(A[n]+B[ssrc[e]])  (smem tile only)
// out  = T @ w2 + (deg+1)*b2 ;  POOL: relu + pool atomics, else store agg.
template <bool POOL>
__global__ void __launch_bounds__(TPB_E, 1)
accum_msg_kernel(const float* __restrict__ A, const float* __restrict__ B,
                 const int* __restrict__ ssrc, const int* __restrict__ start,
                 const float* __restrict__ W2, const float* __restrict__ b2,
                 const int* __restrict__ deg, const int* __restrict__ batch,
                 float* __restrict__ agg, float* __restrict__ pool, int nrows)
{
    extern __shared__ float sm[];
    float* Wb = sm;
    const int tid = threadIdx.x, wid = tid >> 5, lane = tid & 31;
    float* ta = sm + WB_FLOATS + wid * TILE16;

    stage_w_frag(Wb, W2);
    __syncthreads();

    const int gwarp  = blockIdx.x * 16 + wid;
    const int nwarps = gridDim.x * 16;
    const int ntasks = (nrows + 15) / 16;
    const int sbase  = (lane >> 1) * 132 + 2 * (lane & 1);

    for (int task = gwarp; task < ntasks; task += nwarps) {
        const int r0 = task * 16;

        // ---- phase 1: accumulate relu'd messages per node, write tile ----
        for (int e = 0; e < 16; e++) {
            int node = r0 + e;
            float4 acc4 = make_float4(0.f, 0.f, 0.f, 0.f);
            if (node < nrows) {
                float4 a  = ((const float4*)(A + (size_t)node * 128))[lane];
                float4 bs = ((const float4*)(B + (size_t)node * 128))[lane];
                acc4 = relu4(make_float4(a.x + bs.x, a.y + bs.y, a.z + bs.z, a.w + bs.w)); // self loop
                int ei  = __ldg(start + node);
                int ee  = __ldg(start + node + 1);
                for (; ei + 4 <= ee; ei += 4) {
                    int j0 = __ldg(ssrc + ei),     j1 = __ldg(ssrc + ei + 1);
                    int j2 = __ldg(ssrc + ei + 2), j3 = __ldg(ssrc + ei + 3);
                    float4 b0 = ((const float4*)(B + (size_t)j0 * 128))[lane];
                    float4 b1v = ((const float4*)(B + (size_t)j1 * 128))[lane];
                    float4 b2v = ((const float4*)(B + (size_t)j2 * 128))[lane];
                    float4 b3 = ((const float4*)(B + (size_t)j3 * 128))[lane];
                    float4 t0 = relu4(make_float4(a.x + b0.x, a.y + b0.y, a.z + b0.z, a.w + b0.w));
                    float4 t1 = relu4(make_float4(a.x + b1v.x, a.y + b1v.y, a.z + b1v.z, a.w + b1v.w));
                    float4 t2 = relu4(make_float4(a.x + b2v.x, a.y + b2v.y, a.z + b2v.z, a.w + b2v.w));
                    float4 t3 = relu4(make_float4(a.x + b3.x, a.y + b3.y, a.z + b3.z, a.w + b3.w));
                    acc4.x += t0.x + t1.x + t2.x + t3.x;
                    acc4.y += t0.y + t1.y + t2.y + t3.y;
                    acc4.z += t0.z + t1.z + t2.z + t3.z;
                    acc4.w += t0.w + t1.w + t2.w + t3.w;
                }
                for (; ei < ee; ei++) {
                    int j = __ldg(ssrc + ei);
                    float4 b = ((const float4*)(B + (size_t)j * 128))[lane];
                    float4 t = relu4(make_float4(a.x + b.x, a.y + b.y, a.z + b.z, a.w + b.w));
                    acc4.x += t.x; acc4.y += t.y; acc4.z += t.z; acc4.w += t.w;
                }
            }
            float* p = ta + sbase + (e & 7) * 16 + (e >> 3);
            p[0] = acc4.x; p[4] = acc4.y; p[8] = acc4.z; p[12] = acc4.w;
        }
        __syncwarp();

        // ---- phase 2: MMA with w2 (smem) ----
        float4 acc[16];
        mma_mainloop(acc, ta, (const uint4*)Wb, lane);
        __syncwarp();

        // ---- epilogue ----
        int i0 = r0 + (lane >> 2);
        int i1 = i0 + 8;
        float s0 = 0.f, s1 = 0.f;
        int g0 = 0, g1 = 0;
        if (i0 < nrows) { s0 = (float)(__ldg(deg + i0) + 1); if (POOL) g0 = __ldg(batch + i0); }
        if (i1 < nrows) { s1 = (float)(__ldg(deg + i1) + 1); if (POOL) g1 = __ldg(batch + i1); }
        #pragma unroll
        for (int nb = 0; nb < 16; nb++) {
            int c = 2 * (lane & 3) + nb * 8;
            float q0 = __ldg(b2 + c), q1 = __ldg(b2 + c + 1);
            if (POOL) {
                if (i0 < nrows)
                    redv2(pool + (size_t)g0 * 128 + c,
                          fmaxf(acc[nb].x + s0 * q0, 0.f), fmaxf(acc[nb].y + s0 * q1, 0.f));
                if (i1 < nrows)
                    redv2(pool + (size_t)g1 * 128 + c,
                          fmaxf(acc[nb].z + s1 * q0, 0.f), fmaxf(acc[nb].w + s1 * q1, 0.f));
            } else {
                if (i0 < nrows)
                    *(float2*)(agg + (size_t)i0 * 128 + c) = make_float2(acc[nb].x + s0 * q0, acc[nb].y + s0 * q1);
                if (i1 < nrows)
                    *(float2*)(agg + (size_t)i1 * 128 + c) = make_float2(acc[nb].z + s1 * q0, acc[nb].w + s1 * q1);
            }
        }
    }
}

// ======================= CSR / counts / final =======================
__global__ void deg_kernel(const int* __restrict__ dst, int* __restrict__ deg, int E) {
    int i = blockIdx.x * blockDim.x + threadIdx.x;
    if (i < E) atomicAdd(&deg[dst[i]], 1);
}

__global__ void cnt_kernel(const int* __restrict__ batch, float* __restrict__ cnt, int n) {
    int i = blockIdx.x * blockDim.x + threadIdx.x;
    if (i < n) atomicAdd(&cnt[batch[i]], 1.f);
}

__global__ void scan_kernel(const int* __restrict__ deg, int* __restrict__ start,
                            int* __restrict__ cursor, int n)
{
    __shared__ int carry;
    __shared__ int wsum[32];
    const int tidx = threadIdx.x, lane = tidx & 31, wid = tidx >> 5;
    if (tidx == 0) carry = 0;
    __syncthreads();

    for (int base = 0; base < n; base += 1024) {
        int i = base + tidx;
        int v = (i < n) ? deg[i] : 0;
        int x = v;
        #pragma unroll
        for (int o = 1; o < 32; o <<= 1) {
            int y = __shfl_up_sync(0xffffffffu, x, o);
            if (lane >= o) x += y;
        }
        if (lane == 31) wsum[wid] = x;
        __syncthreads();
        if (wid == 0) {
            int w = wsum[lane];
            #pragma unroll
            for (int o = 1; o < 32; o <<= 1) {
                int y = __shfl_up_sync(0xffffffffu, w, o);
                if (lane >= o) w += y;
            }
            wsum[lane] = w;
        }
        __syncthreads();
        int excl = x - v + (wid > 0 ? wsum[wid - 1] : 0) + carry;
        if (i < n) { start[i] = excl; cursor[i] = excl; }
        int blocktot = wsum[31];
        __syncthreads();
        if (tidx == 0) carry += blocktot;
        __syncthreads();
    }
    if (tidx == 0) start[n] = carry;
}

__global__ void scatter_kernel(const int* __restrict__ src, const int* __restrict__ dst,
                               int* __restrict__ cursor, int* __restrict__ ssrc, int E)
{
    int i = blockIdx.x * blockDim.x + threadIdx.x;
    if (i < E) {
        int p = atomicAdd(&cursor[dst[i]], 1);
        ssrc[p] = src[i];
    }
}

__global__ void final_kernel(const float* __restrict__ pool, const float* __restrict__ cnt,
                             const float* __restrict__ W, const float* __restrict__ b,
                             float* __restrict__ out)
{
    __shared__ float p[128];
    int g = blockIdx.x;
    float c = fmaxf(cnt[g], 1.f);
    for (int j = threadIdx.x; j < 128; j += blockDim.x)
        p[j] = pool[(size_t)g * 128 + j] / c;
    __syncthreads();
    int o = threadIdx.x;
    float s = b[o];
    #pragma unroll 4
    for (int j = 0; j < 128; j++) s += p[j] * W[j * 64 + o];
    out[(size_t)g * 64 + o] = s;
}

// ======================= launch =======================
extern "C" void kernel_launch(void* const* d_in, const int* in_sizes, int n_in,
                              void* d_out, int out_size)
{
    const float* x     = (const float*)d_in[0];
    const int*   ei    = (const int*)  d_in[1];
    const int*   batch = (const int*)  d_in[3];
    const int N = in_sizes[0] / 128;
    const int E = in_sizes[1] / 2;
    const int* src = ei;
    const int* dst = ei + E;

    const float* lin_w[3] = { (const float*)d_in[4],  (const float*)d_in[10], (const float*)d_in[16] };
    const float* lin_b[3] = { (const float*)d_in[5],  (const float*)d_in[11], (const float*)d_in[17] };
    const float* w1[3]    = { (const float*)d_in[6],  (const float*)d_in[12], (const float*)d_in[18] };
    const float* b1[3]    = { (const float*)d_in[7],  (const float*)d_in[13], (const float*)d_in[19] };
    const float* w2[3]    = { (const float*)d_in[8],  (const float*)d_in[14], (const float*)d_in[20] };
    const float* b2[3]    = { (const float*)d_in[9],  (const float*)d_in[15], (const float*)d_in[21] };
    const float* out_w    = (const float*)d_in[22];
    const float* out_b    = (const float*)d_in[23];
    float* out = (float*)d_out;

    float *h_, *A_, *B_, *agg_, *pool_, *cnt_;
    int *deg_, *start_, *cursor_, *ssrc_;
    cudaGetSymbolAddress((void**)&h_,     g_h);
    cudaGetSymbolAddress((void**)&A_,     g_A);
    cudaGetSymbolAddress((void**)&B_,     g_B);
    cudaGetSymbolAddress((void**)&agg_,   g_agg);
    cudaGetSymbolAddress((void**)&pool_,  g_pool);
    cudaGetSymbolAddress((void**)&cnt_,   g_cnt);
    cudaGetSymbolAddress((void**)&deg_,   g_deg);
    cudaGetSymbolAddress((void**)&start_, g_start);
    cudaGetSymbolAddress((void**)&cursor_,g_cursor);
    cudaGetSymbolAddress((void**)&ssrc_,  g_ssrc);

    cudaFuncSetAttribute((const void*)node_mma_kernel<false>,
                         cudaFuncAttributeMaxDynamicSharedMemorySize, MMA_SMEM);
    cudaFuncSetAttribute((const void*)node_mma_kernel<true>,
                         cudaFuncAttributeMaxDynamicSharedMemorySize, MMA_SMEM);
    cudaFuncSetAttribute((const void*)accum_msg_kernel<false>,
                         cudaFuncAttributeMaxDynamicSharedMemorySize, MMA_SMEM);
    cudaFuncSetAttribute((const void*)accum_msg_kernel<true>,
                         cudaFuncAttributeMaxDynamicSharedMemorySize, MMA_SMEM);

    const int G = out_size / 64;

    // ---- prep: CSR by dst, graph counts ----
    cudaMemsetAsync(deg_,  0, (size_t)N * sizeof(int));
    cudaMemsetAsync(pool_, 0, (size_t)G * 128 * sizeof(float));
    cudaMemsetAsync(cnt_,  0, (size_t)G * sizeof(float));
    deg_kernel<<<(E + 255) / 256, 256>>>(dst, deg_, E);
    cnt_kernel<<<(N + 255) / 256, 256>>>(batch, cnt_, N);
    scan_kernel<<<1, 1024>>>(deg_, start_, cursor_, N);
    scatter_kernel<<<(E + 255) / 256, 256>>>(src, dst, cursor_, ssrc_, E);

    for (int l = 0; l < 3; l++) {
        const float* X = (l == 0) ? x : agg_;
        if (l == 0)
            node_mma_kernel<false><<<NBLK_G, TPB_E, MMA_SMEM>>>(X, lin_w[l], lin_b[l], h_, N);
        else
            node_mma_kernel<true ><<<NBLK_G, TPB_E, MMA_SMEM>>>(X, lin_w[l], lin_b[l], h_, N);
        node_mma_kernel<false><<<NBLK_G, TPB_E, MMA_SMEM>>>(h_, w1[l],             b1[l],  A_, N);
        node_mma_kernel<false><<<NBLK_G, TPB_E, MMA_SMEM>>>(h_, w1[l] + 128 * 128, nullptr, B_, N);
        if (l < 2)
            accum_msg_kernel<false><<<NBLK_G, TPB_E, MMA_SMEM>>>(A_, B_, ssrc_, start_, w2[l], b2[l],
                                                                 deg_, batch, agg_, pool_, N);
        else
            accum_msg_kernel<true ><<<NBLK_G, TPB_E, MMA_SMEM>>>(A_, B_, ssrc_, start_, w2[l], b2[l],
                                                                 deg_, batch, agg_, pool_, N);
    }

    final_kernel<<<G, 64>>>(pool_, cnt_, out_w, out_b, out);
}

// round 12
// speedup vs baseline: 1.7262x; 1.1604x over previous
#include <cuda_runtime.h>
#include <cstdint>

#define NBLK   148
#define TPB_E  512
#define TILE16 (16*132)                            // 2112 floats per 16-row tile
#define WB_FLOATS (8*16*32*4)                      // 16384 floats = 64 KB (W frag layout)
#define MMA_SMEM ((WB_FLOATS + 16*TILE16) * 4)     // 64KB + 132KB = 200704 B

// Scratch (device globals: allocation-free rule)
__device__ float g_A   [50000 * 128];
__device__ float g_B   [50000 * 128];
__device__ float g_T   [50000 * 128];
__device__ float g_agg [50000 * 128];
__device__ float g_pool[64 * 128];
__device__ float g_cnt [64];
__device__ int   g_deg [50000];
__device__ int   g_start[50001];
__device__ int   g_cursor[50000];
__device__ int   g_ssrc[800000];
__device__ float g_Wc  [6 * 16384];                // composite Wa/Wb per layer (fp32)
__device__ float g_bc  [6 * 128];                  // composite biases

__device__ __forceinline__ float4 relu4(float4 v) {
    v.x = fmaxf(v.x, 0.f); v.y = fmaxf(v.y, 0.f);
    v.z = fmaxf(v.z, 0.f); v.w = fmaxf(v.w, 0.f);
    return v;
}

// ======================= tf32 mma helpers =======================
__device__ __forceinline__ uint32_t f2tf32(float f) {
    uint32_t r; asm("cvt.rna.tf32.f32 %0, %1;" : "=r"(r) : "f"(f)); return r;
}
__device__ __forceinline__ void mma8(float4 &d, const uint32_t a[4],
                                     uint32_t b0, uint32_t b1) {
    asm volatile("mma.sync.aligned.m16n8k8.row.col.f32.tf32.tf32.f32 "
        "{%0,%1,%2,%3}, {%4,%5,%6,%7}, {%8,%9}, {%0,%1,%2,%3};"
        : "+f"(d.x), "+f"(d.y), "+f"(d.z), "+f"(d.w)
        : "r"(a[0]), "r"(a[1]), "r"(a[2]), "r"(a[3]), "r"(b0), "r"(b1));
}
__device__ __forceinline__ void split4hl(float4 v, uint32_t h[4], uint32_t l[4]) {
    h[0] = f2tf32(v.x); l[0] = f2tf32(v.x - __uint_as_float(h[0]));
    h[1] = f2tf32(v.y); l[1] = f2tf32(v.y - __uint_as_float(h[1]));
    h[2] = f2tf32(v.z); l[2] = f2tf32(v.z - __uint_as_float(h[2]));
    h[3] = f2tf32(v.w); l[3] = f2tf32(v.w - __uint_as_float(h[3]));
}

// Stage W (row-major [k][n], 128x128) into B-fragment layout, tf32-rounded.
__device__ __forceinline__ void stage_w_frag(float* Wb, const float* __restrict__ W) {
    for (int i = threadIdx.x; i < 4096; i += TPB_E) {
        int kk2 = i >> 9, rem = i & 511, nb = rem >> 5, ln = rem & 31;
        int n = nb * 8 + (ln >> 2), k = kk2 * 16 + (ln & 3);
        uint4 v;
        v.x = f2tf32(W[(k     ) * 128 + n]);
        v.y = f2tf32(W[(k +  4) * 128 + n]);
        v.z = f2tf32(W[(k +  8) * 128 + n]);
        v.w = f2tf32(W[(k + 12) * 128 + n]);
        ((uint4*)Wb)[i] = v;
    }
}

// m16 x n128 x k128 mainloop over the tile, hi/lo compensated activations.
__device__ __forceinline__ void mma_mainloop(float4 acc[16], const float* ta,
                                             const uint4* wf, int lane) {
    #pragma unroll
    for (int nb = 0; nb < 16; nb++) acc[nb] = make_float4(0.f, 0.f, 0.f, 0.f);
    #pragma unroll
    for (int kk2 = 0; kk2 < 8; kk2++) {
        float4 ve = *(const float4*)(ta + (2 * kk2    ) * 132 + lane * 4);
        float4 vo = *(const float4*)(ta + (2 * kk2 + 1) * 132 + lane * 4);
        uint32_t he[4], le[4], ho[4], lo[4];
        split4hl(ve, he, le);
        split4hl(vo, ho, lo);
        const uint4* wrow = wf + kk2 * 512 + lane;
        #pragma unroll
        for (int nb = 0; nb < 16; nb++) {
            uint4 B = wrow[nb * 32];
            mma8(acc[nb], he, B.x, B.y);
            mma8(acc[nb], le, B.x, B.y);
            mma8(acc[nb], ho, B.z, B.w);
            mma8(acc[nb], lo, B.z, B.w);
        }
    }
}

__device__ __forceinline__ void redv2(float* p, float a, float b) {
    asm volatile("red.global.add.v2.f32 [%0], {%1, %2};" :: "l"(p), "f"(a), "f"(b) : "memory");
}

// ======================= node GEMM: Y[r] = relu_in(X[r]) @ W + bias =======================
template <bool RELU_IN>
__global__ void __launch_bounds__(TPB_E, 1)
node_mma_kernel(const float* __restrict__ X, const float* __restrict__ W,
                const float* __restrict__ bias, float* __restrict__ Y, int nrows)
{
    extern __shared__ float sm[];
    float* Wb = sm;
    const int tid = threadIdx.x, wid = tid >> 5, lane = tid & 31;
    float* ta = sm + WB_FLOATS + wid * TILE16;

    stage_w_frag(Wb, W);
    __syncthreads();

    const int gwarp  = blockIdx.x * 16 + wid;
    const int nwarps = gridDim.x * 16;
    const int ntasks = (nrows + 15) / 16;
    const int sbase  = (lane >> 1) * 132 + 2 * (lane & 1);

    for (int task = gwarp; task < ntasks; task += nwarps) {
        const int r0 = task * 16;

        #pragma unroll 4
        for (int e = 0; e < 16; e++) {
            int r = r0 + e;
            float4 t = make_float4(0.f, 0.f, 0.f, 0.f);
            if (r < nrows) {
                t = ((const float4*)(X + (size_t)r * 128))[lane];
                if (RELU_IN) t = relu4(t);
            }
            float* p = ta + sbase + (e & 7) * 16 + (e >> 3);
            p[0] = t.x; p[4] = t.y; p[8] = t.z; p[12] = t.w;
        }
        __syncwarp();

        float4 acc[16];
        mma_mainloop(acc, ta, (const uint4*)Wb, lane);
        __syncwarp();

        int i0 = r0 + (lane >> 2);
        int i1 = i0 + 8;
        #pragma unroll
        for (int nb = 0; nb < 16; nb++) {
            int c = 2 * (lane & 3) + nb * 8;
            float b0 = 0.f, b1 = 0.f;
            if (bias) { b0 = __ldg(bias + c); b1 = __ldg(bias + c + 1); }
            if (i0 < nrows)
                *(float2*)(Y + (size_t)i0 * 128 + c) = make_float2(acc[nb].x + b0, acc[nb].y + b1);
            if (i1 < nrows)
                *(float2*)(Y + (size_t)i1 * 128 + c) = make_float2(acc[nb].z + b0, acc[nb].w + b1);
        }
    }
}

// ======================= msg GEMM: out = T @ w2 + (deg+1)*b2 =======================
// POOL: relu + mean-pool atomics into pool[batch[r]]; else store agg.
template <bool POOL>
__global__ void __launch_bounds__(TPB_E, 1)
msg_mma_kernel(const float* __restrict__ T, const float* __restrict__ W2,
               const float* __restrict__ b2, const int* __restrict__ deg,
               const int* __restrict__ batch, float* __restrict__ agg,
               float* __restrict__ pool, int nrows)
{
    extern __shared__ float sm[];
    float* Wb = sm;
    const int tid = threadIdx.x, wid = tid >> 5, lane = tid & 31;
    float* ta = sm + WB_FLOATS + wid * TILE16;

    stage_w_frag(Wb, W2);
    __syncthreads();

    const int gwarp  = blockIdx.x * 16 + wid;
    const int nwarps = gridDim.x * 16;
    const int ntasks = (nrows + 15) / 16;
    const int sbase  = (lane >> 1) * 132 + 2 * (lane & 1);

    for (int task = gwarp; task < ntasks; task += nwarps) {
        const int r0 = task * 16;

        #pragma unroll 4
        for (int e = 0; e < 16; e++) {
            int r = r0 + e;
            float4 t = make_float4(0.f, 0.f, 0.f, 0.f);
            if (r < nrows) t = ((const float4*)(T + (size_t)r * 128))[lane];
            float* p = ta + sbase + (e & 7) * 16 + (e >> 3);
            p[0] = t.x; p[4] = t.y; p[8] = t.z; p[12] = t.w;
        }
        __syncwarp();

        float4 acc[16];
        mma_mainloop(acc, ta, (const uint4*)Wb, lane);
        __syncwarp();

        int i0 = r0 + (lane >> 2);
        int i1 = i0 + 8;
        float s0 = 0.f, s1 = 0.f;
        int g0 = 0, g1 = 0;
        if (i0 < nrows) { s0 = (float)(__ldg(deg + i0) + 1); if (POOL) g0 = __ldg(batch + i0); }
        if (i1 < nrows) { s1 = (float)(__ldg(deg + i1) + 1); if (POOL) g1 = __ldg(batch + i1); }
        #pragma unroll
        for (int nb = 0; nb < 16; nb++) {
            int c = 2 * (lane & 3) + nb * 8;
            float q0 = __ldg(b2 + c), q1 = __ldg(b2 + c + 1);
            if (POOL) {
                if (i0 < nrows)
                    redv2(pool + (size_t)g0 * 128 + c,
                          fmaxf(acc[nb].x + s0 * q0, 0.f), fmaxf(acc[nb].y + s0 * q1, 0.f));
                if (i1 < nrows)
                    redv2(pool + (size_t)g1 * 128 + c,
                          fmaxf(acc[nb].z + s1 * q0, 0.f), fmaxf(acc[nb].w + s1 * q1, 0.f));
            } else {
                if (i0 < nrows)
                    *(float2*)(agg + (size_t)i0 * 128 + c) = make_float2(acc[nb].x + s0 * q0, acc[nb].y + s0 * q1);
                if (i1 < nrows)
                    *(float2*)(agg + (size_t)i1 * 128 + c) = make_float2(acc[nb].z + s1 * q0, acc[nb].w + s1 * q1);
            }
        }
    }
}

// ======================= accum (high occupancy, no smem) =======================
// T[n] = relu(A[n]+B[n]) + sum_{e in CSR[n]} relu(A[n]+B[ssrc[e]])
__global__ void __launch_bounds__(512)
accum_kernel(const float* __restrict__ A, const float* __restrict__ B,
             const int* __restrict__ ssrc, const int* __restrict__ start,
             float* __restrict__ T, int n)
{
    const int gw   = (blockIdx.x * blockDim.x + threadIdx.x) >> 5;
    const int lane = threadIdx.x & 31;
    const int nw   = (gridDim.x * blockDim.x) >> 5;

    for (int node = gw; node < n; node += nw) {
        float4 a  = ((const float4*)(A + (size_t)node * 128))[lane];
        float4 bs = ((const float4*)(B + (size_t)node * 128))[lane];
        float4 acc = relu4(make_float4(a.x + bs.x, a.y + bs.y, a.z + bs.z, a.w + bs.w)); // self loop

        int e  = __ldg(start + node);
        int e1 = __ldg(start + node + 1);
        for (; e + 4 <= e1; e += 4) {
            int j0 = __ldg(ssrc + e),     j1 = __ldg(ssrc + e + 1);
            int j2 = __ldg(ssrc + e + 2), j3 = __ldg(ssrc + e + 3);
            float4 b0 = ((const float4*)(B + (size_t)j0 * 128))[lane];
            float4 b1 = ((const float4*)(B + (size_t)j1 * 128))[lane];
            float4 b2 = ((const float4*)(B + (size_t)j2 * 128))[lane];
            float4 b3 = ((const float4*)(B + (size_t)j3 * 128))[lane];
            float4 t0 = relu4(make_float4(a.x + b0.x, a.y + b0.y, a.z + b0.z, a.w + b0.w));
            float4 t1 = relu4(make_float4(a.x + b1.x, a.y + b1.y, a.z + b1.z, a.w + b1.w));
            float4 t2 = relu4(make_float4(a.x + b2.x, a.y + b2.y, a.z + b2.z, a.w + b2.w));
            float4 t3 = relu4(make_float4(a.x + b3.x, a.y + b3.y, a.z + b3.z, a.w + b3.w));
            acc.x += t0.x + t1.x + t2.x + t3.x;
            acc.y += t0.y + t1.y + t2.y + t3.y;
            acc.z += t0.z + t1.z + t2.z + t3.z;
            acc.w += t0.w + t1.w + t2.w + t3.w;
        }
        for (; e < e1; e++) {
            int j = __ldg(ssrc + e);
            float4 b = ((const float4*)(B + (size_t)j * 128))[lane];
            float4 t = relu4(make_float4(a.x + b.x, a.y + b.y, a.z + b.z, a.w + b.w));
            acc.x += t.x; acc.y += t.y; acc.z += t.z; acc.w += t.w;
        }
        ((float4*)(T + (size_t)node * 128))[lane] = acc;
    }
}

// ======================= weight composition (fp32 exact, once per launch) =======================
// out[k][m] = sum_n Wlin[k][n] * w1p[n][m]
__global__ void compose_kernel(const float* __restrict__ Wlin, const float* __restrict__ w1p,
                               float* __restrict__ out)
{
    __shared__ float row[128];
    int k = blockIdx.x, m = threadIdx.x;
    row[m] = Wlin[k * 128 + m];
    __syncthreads();
    float s = 0.f;
    #pragma unroll 8
    for (int n = 0; n < 128; n++) s += row[n] * w1p[n * 128 + m];
    out[k * 128 + m] = s;
}

// out[m] = sum_n lin_b[n]*w1p[n][m] + (b1 ? b1[m] : 0)
__global__ void bias_compose_kernel(const float* __restrict__ lin_b, const float* __restrict__ w1p,
                                    const float* __restrict__ b1, float* __restrict__ out)
{
    int m = threadIdx.x;
    float s = b1 ? b1[m] : 0.f;
    #pragma unroll 8
    for (int n = 0; n < 128; n++) s += lin_b[n] * w1p[n * 128 + m];
    out[m] = s;
}

// ======================= CSR / counts / final =======================
__global__ void deg_kernel(const int* __restrict__ dst, int* __restrict__ deg, int E) {
    int i = blockIdx.x * blockDim.x + threadIdx.x;
    if (i < E) atomicAdd(&deg[dst[i]], 1);
}

__global__ void cnt_kernel(const int* __restrict__ batch, float* __restrict__ cnt, int n) {
    int i = blockIdx.x * blockDim.x + threadIdx.x;
    if (i < n) atomicAdd(&cnt[batch[i]], 1.f);
}

__global__ void scan_kernel(const int* __restrict__ deg, int* __restrict__ start,
                            int* __restrict__ cursor, int n)
{
    __shared__ int carry;
    __shared__ int wsum[32];
    const int tidx = threadIdx.x, lane = tidx & 31, wid = tidx >> 5;
    if (tidx == 0) carry = 0;
    __syncthreads();

    for (int base = 0; base < n; base += 1024) {
        int i = base + tidx;
        int v = (i < n) ? deg[i] : 0;
        int x = v;
        #pragma unroll
        for (int o = 1; o < 32; o <<= 1) {
            int y = __shfl_up_sync(0xffffffffu, x, o);
            if (lane >= o) x += y;
        }
        if (lane == 31) wsum[wid] = x;
        __syncthreads();
        if (wid == 0) {
            int w = wsum[lane];
            #pragma unroll
            for (int o = 1; o < 32; o <<= 1) {
                int y = __shfl_up_sync(0xffffffffu, w, o);
                if (lane >= o) w += y;
            }
            wsum[lane] = w;
        }
        __syncthreads();
        int excl = x - v + (wid > 0 ? wsum[wid - 1] : 0) + carry;
        if (i < n) { start[i] = excl; cursor[i] = excl; }
        int blocktot = wsum[31];
        __syncthreads();
        if (tidx == 0) carry += blocktot;
        __syncthreads();
    }
    if (tidx == 0) start[n] = carry;
}

__global__ void scatter_kernel(const int* __restrict__ src, const int* __restrict__ dst,
                               int* __restrict__ cursor, int* __restrict__ ssrc, int E)
{
    int i = blockIdx.x * blockDim.x + threadIdx.x;
    if (i < E) {
        int p = atomicAdd(&cursor[dst[i]], 1);
        ssrc[p] = src[i];
    }
}

__global__ void final_kernel(const float* __restrict__ pool, const float* __restrict__ cnt,
                             const float* __restrict__ W, const float* __restrict__ b,
                             float* __restrict__ out)
{
    __shared__ float p[128];
    int g = blockIdx.x;
    float c = fmaxf(cnt[g], 1.f);
    for (int j = threadIdx.x; j < 128; j += blockDim.x)
        p[j] = pool[(size_t)g * 128 + j] / c;
    __syncthreads();
    int o = threadIdx.x;
    float s = b[o];
    #pragma unroll 4
    for (int j = 0; j < 128; j++) s += p[j] * W[j * 64 + o];
    out[(size_t)g * 64 + o] = s;
}

// ======================= launch =======================
extern "C" void kernel_launch(void* const* d_in, const int* in_sizes, int n_in,
                              void* d_out, int out_size)
{
    const float* x     = (const float*)d_in[0];
    const int*   ei    = (const int*)  d_in[1];
    const int*   batch = (const int*)  d_in[3];
    const int N = in_sizes[0] / 128;
    const int E = in_sizes[1] / 2;
    const int* src = ei;
    const int* dst = ei + E;

    const float* lin_w[3] = { (const float*)d_in[4],  (const float*)d_in[10], (const float*)d_in[16] };
    const float* lin_b[3] = { (const float*)d_in[5],  (const float*)d_in[11], (const float*)d_in[17] };
    const float* w1[3]    = { (const float*)d_in[6],  (const float*)d_in[12], (const float*)d_in[18] };
    const float* b1[3]    = { (const float*)d_in[7],  (const float*)d_in[13], (const float*)d_in[19] };
    const float* w2[3]    = { (const float*)d_in[8],  (const float*)d_in[14], (const float*)d_in[20] };
    const float* b2[3]    = { (const float*)d_in[9],  (const float*)d_in[15], (const float*)d_in[21] };
    const float* out_w    = (const float*)d_in[22];
    const float* out_b    = (const float*)d_in[23];
    float* out = (float*)d_out;

    float *A_, *B_, *T_, *agg_, *pool_, *cnt_, *Wc_, *bc_;
    int *deg_, *start_, *cursor_, *ssrc_;
    cudaGetSymbolAddress((void**)&A_,     g_A);
    cudaGetSymbolAddress((void**)&B_,     g_B);
    cudaGetSymbolAddress((void**)&T_,     g_T);
    cudaGetSymbolAddress((void**)&agg_,   g_agg);
    cudaGetSymbolAddress((void**)&pool_,  g_pool);
    cudaGetSymbolAddress((void**)&cnt_,   g_cnt);
    cudaGetSymbolAddress((void**)&deg_,   g_deg);
    cudaGetSymbolAddress((void**)&start_, g_start);
    cudaGetSymbolAddress((void**)&cursor_,g_cursor);
    cudaGetSymbolAddress((void**)&ssrc_,  g_ssrc);
    cudaGetSymbolAddress((void**)&Wc_,    g_Wc);
    cudaGetSymbolAddress((void**)&bc_,    g_bc);

    cudaFuncSetAttribute((const void*)node_mma_kernel<false>,
                         cudaFuncAttributeMaxDynamicSharedMemorySize, MMA_SMEM);
    cudaFuncSetAttribute((const void*)node_mma_kernel<true>,
                         cudaFuncAttributeMaxDynamicSharedMemorySize, MMA_SMEM);
    cudaFuncSetAttribute((const void*)msg_mma_kernel<false>,
                         cudaFuncAttributeMaxDynamicSharedMemorySize, MMA_SMEM);
    cudaFuncSetAttribute((const void*)msg_mma_kernel<true>,
                         cudaFuncAttributeMaxDynamicSharedMemorySize, MMA_SMEM);

    const int G = out_size / 64;

    // ---- prep: CSR by dst, counts, composite weights ----
    cudaMemsetAsync(deg_,  0, (size_t)N * sizeof(int));
    cudaMemsetAsync(pool_, 0, (size_t)G * 128 * sizeof(float));
    cudaMemsetAsync(cnt_,  0, (size_t)G * sizeof(float));
    deg_kernel<<<(E + 255) / 256, 256>>>(dst, deg_, E);
    cnt_kernel<<<(N + 255) / 256, 256>>>(batch, cnt_, N);
    scan_kernel<<<1, 1024>>>(deg_, start_, cursor_, N);
    scatter_kernel<<<(E + 255) / 256, 256>>>(src, dst, cursor_, ssrc_, E);
    for (int l = 0; l < 3; l++) {
        const float* w1t = w1[l];
        const float* w1b = w1[l] + 128 * 128;
        compose_kernel<<<128, 128>>>(lin_w[l], w1t, Wc_ + (2 * l    ) * 16384);
        compose_kernel<<<128, 128>>>(lin_w[l], w1b, Wc_ + (2 * l + 1) * 16384);
        bias_compose_kernel<<<1, 128>>>(lin_b[l], w1t, b1[l],  bc_ + (2 * l    ) * 128);
        bias_compose_kernel<<<1, 128>>>(lin_b[l], w1b, nullptr, bc_ + (2 * l + 1) * 128);
    }

    for (int l = 0; l < 3; l++) {
        const float* X  = (l == 0) ? x : agg_;
        const float* Wa = Wc_ + (2 * l    ) * 16384;
        const float* Wb = Wc_ + (2 * l + 1) * 16384;
        const float* ba = bc_ + (2 * l    ) * 128;
        const float* bb = bc_ + (2 * l + 1) * 128;
        if (l == 0) {
            node_mma_kernel<false><<<NBLK, TPB_E, MMA_SMEM>>>(X, Wa, ba, A_, N);
            node_mma_kernel<false><<<NBLK, TPB_E, MMA_SMEM>>>(X, Wb, bb, B_, N);
        } else {
            node_mma_kernel<true ><<<NBLK, TPB_E, MMA_SMEM>>>(X, Wa, ba, A_, N);
            node_mma_kernel<true ><<<NBLK, TPB_E, MMA_SMEM>>>(X, Wb, bb, B_, N);
        }
        accum_kernel<<<296, 512>>>(A_, B_, ssrc_, start_, T_, N);
        if (l < 2)
            msg_mma_kernel<false><<<NBLK, TPB_E, MMA_SMEM>>>(T_, w2[l], b2[l], deg_, batch, agg_, pool_, N);
        else
            msg_mma_kernel<true ><<<NBLK, TPB_E, MMA_SMEM>>>(T_, w2[l], b2[l], deg_, batch, agg_, pool_, N);
    }

    final_kernel<<<G, 64>>>(pool_, cnt_, out_w, out_b, out);
}

// round 13
// speedup vs baseline: 2.1336x; 1.2360x over previous
#include <cuda_runtime.h>
#include <cstdint>

#define NBLK    148
// msg kernel: 16 warps, one W bank
#define TPB_M   512
#define TILE16  (16*132)                           // 2112 floats per 16-row tile
#define WB_FLOATS (8*16*32*4)                      // 16384 floats = 64 KB per W bank
#define MSG_SMEM ((WB_FLOATS + 16*TILE16) * 4)     // 200704 B
// AB kernel: 11 warps, two W banks
#define TPB_AB  352
#define NW_AB   11
#define AB_SMEM ((2*WB_FLOATS + NW_AB*TILE16) * 4) // 224000 B

// Scratch (device globals: allocation-free rule)
__device__ float g_A   [50000 * 128];
__device__ float g_B   [50000 * 128];
__device__ float g_T   [50000 * 128];
__device__ float g_agg [50000 * 128];
__device__ float g_pool[64 * 128];
__device__ float g_cnt [64];
__device__ int   g_deg [50000];
__device__ int   g_start[50001];
__device__ int   g_cursor[50000];
__device__ int   g_ssrc[800000];
__device__ float g_Wc  [6 * 16384];                // composite Wa/Wb per layer (fp32)
__device__ float g_bc  [6 * 128];                  // composite biases

__device__ __forceinline__ float4 relu4(float4 v) {
    v.x = fmaxf(v.x, 0.f); v.y = fmaxf(v.y, 0.f);
    v.z = fmaxf(v.z, 0.f); v.w = fmaxf(v.w, 0.f);
    return v;
}

// ======================= tf32 mma helpers =======================
__device__ __forceinline__ uint32_t f2tf32(float f) {
    uint32_t r; asm("cvt.rna.tf32.f32 %0, %1;" : "=r"(r) : "f"(f)); return r;
}
__device__ __forceinline__ void mma8(float4 &d, const uint32_t a[4],
                                     uint32_t b0, uint32_t b1) {
    asm volatile("mma.sync.aligned.m16n8k8.row.col.f32.tf32.tf32.f32 "
        "{%0,%1,%2,%3}, {%4,%5,%6,%7}, {%8,%9}, {%0,%1,%2,%3};"
        : "+f"(d.x), "+f"(d.y), "+f"(d.z), "+f"(d.w)
        : "r"(a[0]), "r"(a[1]), "r"(a[2]), "r"(a[3]), "r"(b0), "r"(b1));
}
__device__ __forceinline__ void cvt4(float4 v, uint32_t h[4]) {
    h[0] = f2tf32(v.x); h[1] = f2tf32(v.y); h[2] = f2tf32(v.z); h[3] = f2tf32(v.w);
}

// Stage W (row-major [k][n], 128x128) into B-fragment layout, tf32-rounded.
__device__ __forceinline__ void stage_w_frag(float* Wb, const float* __restrict__ W) {
    for (int i = threadIdx.x; i < 4096; i += blockDim.x) {
        int kk2 = i >> 9, rem = i & 511, nb = rem >> 5, ln = rem & 31;
        int n = nb * 8 + (ln >> 2), k = kk2 * 16 + (ln & 3);
        uint4 v;
        v.x = f2tf32(W[(k     ) * 128 + n]);
        v.y = f2tf32(W[(k +  4) * 128 + n]);
        v.z = f2tf32(W[(k +  8) * 128 + n]);
        v.w = f2tf32(W[(k + 12) * 128 + n]);
        ((uint4*)Wb)[i] = v;
    }
}

// Single-pass m16 x n128 x k128 mainloop (activations tf32-rounded, no lo pass).
__device__ __forceinline__ void mma_mainloop1(float4 acc[16], const float* ta,
                                              const uint4* wf, int lane) {
    #pragma unroll
    for (int nb = 0; nb < 16; nb++) acc[nb] = make_float4(0.f, 0.f, 0.f, 0.f);
    #pragma unroll
    for (int kk2 = 0; kk2 < 8; kk2++) {
        float4 ve = *(const float4*)(ta + (2 * kk2    ) * 132 + lane * 4);
        float4 vo = *(const float4*)(ta + (2 * kk2 + 1) * 132 + lane * 4);
        uint32_t he[4], ho[4];
        cvt4(ve, he);
        cvt4(vo, ho);
        const uint4* wrow = wf + kk2 * 512 + lane;
        #pragma unroll
        for (int nb = 0; nb < 16; nb++) {
            uint4 B = wrow[nb * 32];
            mma8(acc[nb], he, B.x, B.y);
            mma8(acc[nb], ho, B.z, B.w);
        }
    }
}

__device__ __forceinline__ void redv2(float* p, float a, float b) {
    asm volatile("red.global.add.v2.f32 [%0], {%1, %2};" :: "l"(p), "f"(a), "f"(b) : "memory");
}

// ======================= AB GEMM: A = relu_in(X)@Wa + ba ; B = relu_in(X)@Wb + bb =======================
template <bool RELU_IN>
__global__ void __launch_bounds__(TPB_AB, 1)
ab_mma_kernel(const float* __restrict__ X, const float* __restrict__ Wa,
              const float* __restrict__ Wbm, const float* __restrict__ ba,
              const float* __restrict__ bb, float* __restrict__ Aout,
              float* __restrict__ Bout, int nrows)
{
    extern __shared__ float sm[];
    float* WbankA = sm;
    float* WbankB = sm + WB_FLOATS;
    const int tid = threadIdx.x, wid = tid >> 5, lane = tid & 31;
    float* ta = sm + 2 * WB_FLOATS + wid * TILE16;

    stage_w_frag(WbankA, Wa);
    stage_w_frag(WbankB, Wbm);
    __syncthreads();

    const int gwarp  = blockIdx.x * NW_AB + wid;
    const int nwarps = gridDim.x * NW_AB;
    const int ntasks = (nrows + 15) / 16;
    const int sbase  = (lane >> 1) * 132 + 2 * (lane & 1);

    for (int task = gwarp; task < ntasks; task += nwarps) {
        const int r0 = task * 16;

        #pragma unroll 4
        for (int e = 0; e < 16; e++) {
            int r = r0 + e;
            float4 t = make_float4(0.f, 0.f, 0.f, 0.f);
            if (r < nrows) {
                t = ((const float4*)(X + (size_t)r * 128))[lane];
                if (RELU_IN) t = relu4(t);
            }
            float* p = ta + sbase + (e & 7) * 16 + (e >> 3);
            p[0] = t.x; p[4] = t.y; p[8] = t.z; p[12] = t.w;
        }
        __syncwarp();

        const int i0 = r0 + (lane >> 2);
        const int i1 = i0 + 8;
        float4 acc[16];

        // ---- A output ----
        mma_mainloop1(acc, ta, (const uint4*)WbankA, lane);
        #pragma unroll
        for (int nb = 0; nb < 16; nb++) {
            int c = 2 * (lane & 3) + nb * 8;
            float b0 = __ldg(ba + c), b1 = __ldg(ba + c + 1);
            if (i0 < nrows)
                *(float2*)(Aout + (size_t)i0 * 128 + c) = make_float2(acc[nb].x + b0, acc[nb].y + b1);
            if (i1 < nrows)
                *(float2*)(Aout + (size_t)i1 * 128 + c) = make_float2(acc[nb].z + b0, acc[nb].w + b1);
        }

        // ---- B output ----
        mma_mainloop1(acc, ta, (const uint4*)WbankB, lane);
        #pragma unroll
        for (int nb = 0; nb < 16; nb++) {
            int c = 2 * (lane & 3) + nb * 8;
            float b0 = __ldg(bb + c), b1 = __ldg(bb + c + 1);
            if (i0 < nrows)
                *(float2*)(Bout + (size_t)i0 * 128 + c) = make_float2(acc[nb].x + b0, acc[nb].y + b1);
            if (i1 < nrows)
                *(float2*)(Bout + (size_t)i1 * 128 + c) = make_float2(acc[nb].z + b0, acc[nb].w + b1);
        }
        __syncwarp();
    }
}

// ======================= msg GEMM: out = T @ w2 + (deg+1)*b2 =======================
// POOL: relu + mean-pool atomics into pool[batch[r]]; else store agg.
template <bool POOL>
__global__ void __launch_bounds__(TPB_M, 1)
msg_mma_kernel(const float* __restrict__ T, const float* __restrict__ W2,
               const float* __restrict__ b2, const int* __restrict__ deg,
               const int* __restrict__ batch, float* __restrict__ agg,
               float* __restrict__ pool, int nrows)
{
    extern __shared__ float sm[];
    float* Wb = sm;
    const int tid = threadIdx.x, wid = tid >> 5, lane = tid & 31;
    float* ta = sm + WB_FLOATS + wid * TILE16;

    stage_w_frag(Wb, W2);
    __syncthreads();

    const int gwarp  = blockIdx.x * 16 + wid;
    const int nwarps = gridDim.x * 16;
    const int ntasks = (nrows + 15) / 16;
    const int sbase  = (lane >> 1) * 132 + 2 * (lane & 1);

    for (int task = gwarp; task < ntasks; task += nwarps) {
        const int r0 = task * 16;

        #pragma unroll 4
        for (int e = 0; e < 16; e++) {
            int r = r0 + e;
            float4 t = make_float4(0.f, 0.f, 0.f, 0.f);
            if (r < nrows) t = ((const float4*)(T + (size_t)r * 128))[lane];
            float* p = ta + sbase + (e & 7) * 16 + (e >> 3);
            p[0] = t.x; p[4] = t.y; p[8] = t.z; p[12] = t.w;
        }
        __syncwarp();

        float4 acc[16];
        mma_mainloop1(acc, ta, (const uint4*)Wb, lane);
        __syncwarp();

        int i0 = r0 + (lane >> 2);
        int i1 = i0 + 8;
        float s0 = 0.f, s1 = 0.f;
        int g0 = 0, g1 = 0;
        if (i0 < nrows) { s0 = (float)(__ldg(deg + i0) + 1); if (POOL) g0 = __ldg(batch + i0); }
        if (i1 < nrows) { s1 = (float)(__ldg(deg + i1) + 1); if (POOL) g1 = __ldg(batch + i1); }
        #pragma unroll
        for (int nb = 0; nb < 16; nb++) {
            int c = 2 * (lane & 3) + nb * 8;
            float q0 = __ldg(b2 + c), q1 = __ldg(b2 + c + 1);
            if (POOL) {
                if (i0 < nrows)
                    redv2(pool + (size_t)g0 * 128 + c,
                          fmaxf(acc[nb].x + s0 * q0, 0.f), fmaxf(acc[nb].y + s0 * q1, 0.f));
                if (i1 < nrows)
                    redv2(pool + (size_t)g1 * 128 + c,
                          fmaxf(acc[nb].z + s1 * q0, 0.f), fmaxf(acc[nb].w + s1 * q1, 0.f));
            } else {
                if (i0 < nrows)
                    *(float2*)(agg + (size_t)i0 * 128 + c) = make_float2(acc[nb].x + s0 * q0, acc[nb].y + s0 * q1);
                if (i1 < nrows)
                    *(float2*)(agg + (size_t)i1 * 128 + c) = make_float2(acc[nb].z + s1 * q0, acc[nb].w + s1 * q1);
            }
        }
    }
}

// ======================= accum (high occupancy, no smem) =======================
// T[n] = relu(A[n]+B[n]) + sum_{e in CSR[n]} relu(A[n]+B[ssrc[e]])
__global__ void __launch_bounds__(512)
accum_kernel(const float* __restrict__ A, const float* __restrict__ B,
             const int* __restrict__ ssrc, const int* __restrict__ start,
             float* __restrict__ T, int n)
{
    const int gw   = (blockIdx.x * blockDim.x + threadIdx.x) >> 5;
    const int lane = threadIdx.x & 31;
    const int nw   = (gridDim.x * blockDim.x) >> 5;

    for (int node = gw; node < n; node += nw) {
        float4 a  = ((const float4*)(A + (size_t)node * 128))[lane];
        float4 bs = ((const float4*)(B + (size_t)node * 128))[lane];
        float4 acc = relu4(make_float4(a.x + bs.x, a.y + bs.y, a.z + bs.z, a.w + bs.w)); // self loop

        int e  = __ldg(start + node);
        int e1 = __ldg(start + node + 1);
        for (; e + 4 <= e1; e += 4) {
            int j0 = __ldg(ssrc + e),     j1 = __ldg(ssrc + e + 1);
            int j2 = __ldg(ssrc + e + 2), j3 = __ldg(ssrc + e + 3);
            float4 b0 = ((const float4*)(B + (size_t)j0 * 128))[lane];
            float4 b1 = ((const float4*)(B + (size_t)j1 * 128))[lane];
            float4 b2 = ((const float4*)(B + (size_t)j2 * 128))[lane];
            float4 b3 = ((const float4*)(B + (size_t)j3 * 128))[lane];
            float4 t0 = relu4(make_float4(a.x + b0.x, a.y + b0.y, a.z + b0.z, a.w + b0.w));
            float4 t1 = relu4(make_float4(a.x + b1.x, a.y + b1.y, a.z + b1.z, a.w + b1.w));
            float4 t2 = relu4(make_float4(a.x + b2.x, a.y + b2.y, a.z + b2.z, a.w + b2.w));
            float4 t3 = relu4(make_float4(a.x + b3.x, a.y + b3.y, a.z + b3.z, a.w + b3.w));
            acc.x += t0.x + t1.x + t2.x + t3.x;
            acc.y += t0.y + t1.y + t2.y + t3.y;
            acc.z += t0.z + t1.z + t2.z + t3.z;
            acc.w += t0.w + t1.w + t2.w + t3.w;
        }
        for (; e < e1; e++) {
            int j = __ldg(ssrc + e);
            float4 b = ((const float4*)(B + (size_t)j * 128))[lane];
            float4 t = relu4(make_float4(a.x + b.x, a.y + b.y, a.z + b.z, a.w + b.w));
            acc.x += t.x; acc.y += t.y; acc.z += t.z; acc.w += t.w;
        }
        ((float4*)(T + (size_t)node * 128))[lane] = acc;
    }
}

// ======================= weight composition (fp32 exact, once per launch) =======================
__global__ void compose_kernel(const float* __restrict__ Wlin, const float* __restrict__ w1p,
                               float* __restrict__ out)
{
    __shared__ float row[128];
    int k = blockIdx.x, m = threadIdx.x;
    row[m] = Wlin[k * 128 + m];
    __syncthreads();
    float s = 0.f;
    #pragma unroll 8
    for (int n = 0; n < 128; n++) s += row[n] * w1p[n * 128 + m];
    out[k * 128 + m] = s;
}

__global__ void bias_compose_kernel(const float* __restrict__ lin_b, const float* __restrict__ w1p,
                                    const float* __restrict__ b1, float* __restrict__ out)
{
    int m = threadIdx.x;
    float s = b1 ? b1[m] : 0.f;
    #pragma unroll 8
    for (int n = 0; n < 128; n++) s += lin_b[n] * w1p[n * 128 + m];
    out[m] = s;
}

// ======================= CSR / counts / final =======================
__global__ void deg_kernel(const int* __restrict__ dst, int* __restrict__ deg, int E) {
    int i = blockIdx.x * blockDim.x + threadIdx.x;
    if (i < E) atomicAdd(&deg[dst[i]], 1);
}

__global__ void cnt_kernel(const int* __restrict__ batch, float* __restrict__ cnt, int n) {
    int i = blockIdx.x * blockDim.x + threadIdx.x;
    if (i < n) atomicAdd(&cnt[batch[i]], 1.f);
}

__global__ void scan_kernel(const int* __restrict__ deg, int* __restrict__ start,
                            int* __restrict__ cursor, int n)
{
    __shared__ int carry;
    __shared__ int wsum[32];
    const int tidx = threadIdx.x, lane = tidx & 31, wid = tidx >> 5;
    if (tidx == 0) carry = 0;
    __syncthreads();

    for (int base = 0; base < n; base += 1024) {
        int i = base + tidx;
        int v = (i < n) ? deg[i] : 0;
        int x = v;
        #pragma unroll
        for (int o = 1; o < 32; o <<= 1) {
            int y = __shfl_up_sync(0xffffffffu, x, o);
            if (lane >= o) x += y;
        }
        if (lane == 31) wsum[wid] = x;
        __syncthreads();
        if (wid == 0) {
            int w = wsum[lane];
            #pragma unroll
            for (int o = 1; o < 32; o <<= 1) {
                int y = __shfl_up_sync(0xffffffffu, w, o);
                if (lane >= o) w += y;
            }
            wsum[lane] = w;
        }
        __syncthreads();
        int excl = x - v + (wid > 0 ? wsum[wid - 1] : 0) + carry;
        if (i < n) { start[i] = excl; cursor[i] = excl; }
        int blocktot = wsum[31];
        __syncthreads();
        if (tidx == 0) carry += blocktot;
        __syncthreads();
    }
    if (tidx == 0) start[n] = carry;
}

__global__ void scatter_kernel(const int* __restrict__ src, const int* __restrict__ dst,
                               int* __restrict__ cursor, int* __restrict__ ssrc, int E)
{
    int i = blockIdx.x * blockDim.x + threadIdx.x;
    if (i < E) {
        int p = atomicAdd(&cursor[dst[i]], 1);
        ssrc[p] = src[i];
    }
}

__global__ void final_kernel(const float* __restrict__ pool, const float* __restrict__ cnt,
                             const float* __restrict__ W, const float* __restrict__ b,
                             float* __restrict__ out)
{
    __shared__ float p[128];
    int g = blockIdx.x;
    float c = fmaxf(cnt[g], 1.f);
    for (int j = threadIdx.x; j < 128; j += blockDim.x)
        p[j] = pool[(size_t)g * 128 + j] / c;
    __syncthreads();
    int o = threadIdx.x;
    float s = b[o];
    #pragma unroll 4
    for (int j = 0; j < 128; j++) s += p[j] * W[j * 64 + o];
    out[(size_t)g * 64 + o] = s;
}

// ======================= launch =======================
extern "C" void kernel_launch(void* const* d_in, const int* in_sizes, int n_in,
                              void* d_out, int out_size)
{
    const float* x     = (const float*)d_in[0];
    const int*   ei    = (const int*)  d_in[1];
    const int*   batch = (const int*)  d_in[3];
    const int N = in_sizes[0] / 128;
    const int E = in_sizes[1] / 2;
    const int* src = ei;
    const int* dst = ei + E;

    const float* lin_w[3] = { (const float*)d_in[4],  (const float*)d_in[10], (const float*)d_in[16] };
    const float* lin_b[3] = { (const float*)d_in[5],  (const float*)d_in[11], (const float*)d_in[17] };
    const float* w1[3]    = { (const float*)d_in[6],  (const float*)d_in[12], (const float*)d_in[18] };
    const float* b1[3]    = { (const float*)d_in[7],  (const float*)d_in[13], (const float*)d_in[19] };
    const float* w2[3]    = { (const float*)d_in[8],  (const float*)d_in[14], (const float*)d_in[20] };
    const float* b2[3]    = { (const float*)d_in[9],  (const float*)d_in[15], (const float*)d_in[21] };
    const float* out_w    = (const float*)d_in[22];
    const float* out_b    = (const float*)d_in[23];
    float* out = (float*)d_out;

    float *A_, *B_, *T_, *agg_, *pool_, *cnt_, *Wc_, *bc_;
    int *deg_, *start_, *cursor_, *ssrc_;
    cudaGetSymbolAddress((void**)&A_,     g_A);
    cudaGetSymbolAddress((void**)&B_,     g_B);
    cudaGetSymbolAddress((void**)&T_,     g_T);
    cudaGetSymbolAddress((void**)&agg_,   g_agg);
    cudaGetSymbolAddress((void**)&pool_,  g_pool);
    cudaGetSymbolAddress((void**)&cnt_,   g_cnt);
    cudaGetSymbolAddress((void**)&deg_,   g_deg);
    cudaGetSymbolAddress((void**)&start_, g_start);
    cudaGetSymbolAddress((void**)&cursor_,g_cursor);
    cudaGetSymbolAddress((void**)&ssrc_,  g_ssrc);
    cudaGetSymbolAddress((void**)&Wc_,    g_Wc);
    cudaGetSymbolAddress((void**)&bc_,    g_bc);

    cudaFuncSetAttribute((const void*)ab_mma_kernel<false>,
                         cudaFuncAttributeMaxDynamicSharedMemorySize, AB_SMEM);
    cudaFuncSetAttribute((const void*)ab_mma_kernel<true>,
                         cudaFuncAttributeMaxDynamicSharedMemorySize, AB_SMEM);
    cudaFuncSetAttribute((const void*)msg_mma_kernel<false>,
                         cudaFuncAttributeMaxDynamicSharedMemorySize, MSG_SMEM);
    cudaFuncSetAttribute((const void*)msg_mma_kernel<true>,
                         cudaFuncAttributeMaxDynamicSharedMemorySize, MSG_SMEM);

    const int G = out_size / 64;

    // ---- prep: CSR by dst, counts, composite weights ----
    cudaMemsetAsync(deg_,  0, (size_t)N * sizeof(int));
    cudaMemsetAsync(pool_, 0, (size_t)G * 128 * sizeof(float));
    cudaMemsetAsync(cnt_,  0, (size_t)G * sizeof(float));
    deg_kernel<<<(E + 255) / 256, 256>>>(dst, deg_, E);
    cnt_kernel<<<(N + 255) / 256, 256>>>(batch, cnt_, N);
    scan_kernel<<<1, 1024>>>(deg_, start_, cursor_, N);
    scatter_kernel<<<(E + 255) / 256, 256>>>(src, dst, cursor_, ssrc_, E);
    for (int l = 0; l < 3; l++) {
        const float* w1t = w1[l];
        const float* w1b = w1[l] + 128 * 128;
        compose_kernel<<<128, 128>>>(lin_w[l], w1t, Wc_ + (2 * l    ) * 16384);
        compose_kernel<<<128, 128>>>(lin_w[l], w1b, Wc_ + (2 * l + 1) * 16384);
        bias_compose_kernel<<<1, 128>>>(lin_b[l], w1t, b1[l],  bc_ + (2 * l    ) * 128);
        bias_compose_kernel<<<1, 128>>>(lin_b[l], w1b, nullptr, bc_ + (2 * l + 1) * 128);
    }

    for (int l = 0; l < 3; l++) {
        const float* X  = (l == 0) ? x : agg_;
        const float* Wa = Wc_ + (2 * l    ) * 16384;
        const float* Wb = Wc_ + (2 * l + 1) * 16384;
        const float* ba = bc_ + (2 * l    ) * 128;
        const float* bb = bc_ + (2 * l + 1) * 128;
        if (l == 0)
            ab_mma_kernel<false><<<NBLK, TPB_AB, AB_SMEM>>>(X, Wa, Wb, ba, bb, A_, B_, N);
        else
            ab_mma_kernel<true ><<<NBLK, TPB_AB, AB_SMEM>>>(X, Wa, Wb, ba, bb, A_, B_, N);
        accum_kernel<<<296, 512>>>(A_, B_, ssrc_, start_, T_, N);
        if (l < 2)
            msg_mma_kernel<false><<<NBLK, TPB_M, MSG_SMEM>>>(T_, w2[l], b2[l], deg_, batch, agg_, pool_, N);
        else
            msg_mma_kernel<true ><<<NBLK, TPB_M, MSG_SMEM>>>(T_, w2[l], b2[l], deg_, batch, agg_, pool_, N);
    }

    final_kernel<<<G, 64>>>(pool_, cnt_, out_w, out_b, out);
}

// round 14
// speedup vs baseline: 2.2609x; 1.0597x over previous
#include <cuda_runtime.h>
#include <cstdint>

#define NBLK    148
#define TPB     512
#define TILE_B  (8*528)                            // 4224 bytes per warp tile (fp16)
#define WBANK_U2 4096                              // uint2 entries per W bank (32 KB)
#define MSG_SMEM (32768 + 16*TILE_B)               // 100352 B
#define AB_SMEM  (65536 + 16*TILE_B)               // 133120 B

// Scratch (device globals: allocation-free rule)
__device__ float g_A   [50000 * 128];
__device__ float g_B   [50000 * 128];
__device__ float g_T   [50000 * 128];
__device__ float g_agg [50000 * 128];
__device__ float g_pool[64 * 128];
__device__ float g_cnt [64];
__device__ int   g_deg [50000];
__device__ int   g_start[50001];
__device__ int   g_cursor[50000];
__device__ int   g_ssrc[800000];
__device__ float g_Wc  [6 * 16384];                // composite Wa/Wb per layer (fp32)
__device__ float g_bc  [6 * 128];                  // composite biases

__device__ __forceinline__ float4 relu4(float4 v) {
    v.x = fmaxf(v.x, 0.f); v.y = fmaxf(v.y, 0.f);
    v.z = fmaxf(v.z, 0.f); v.w = fmaxf(v.w, 0.f);
    return v;
}

// ======================= fp16 mma helpers =======================
// pack: d[15:0] = lo, d[31:16] = hi   (cvt.rn.f16x2.f32 d, hi, lo)
__device__ __forceinline__ uint32_t packh2(float lo, float hi) {
    uint32_t r;
    asm("cvt.rn.f16x2.f32 %0, %1, %2;" : "=r"(r) : "f"(hi), "f"(lo));
    return r;
}
__device__ __forceinline__ void mma16(float4 &d, uint4 a, uint2 b) {
    asm volatile("mma.sync.aligned.m16n8k16.row.col.f32.f16.f16.f32 "
        "{%0,%1,%2,%3}, {%4,%5,%6,%7}, {%8,%9}, {%0,%1,%2,%3};"
        : "+f"(d.x), "+f"(d.y), "+f"(d.z), "+f"(d.w)
        : "r"(a.x), "r"(a.y), "r"(a.z), "r"(a.w), "r"(b.x), "r"(b.y));
}

// Stage W (row-major [k][n], 128x128, fp32) into fp16 B-fragment bank.
// entry i: ks = i>>9, nb = (i>>5)&15, lid = i&31
//   n = nb*8 + (lid>>2); k0 = ks*16 + (lid&3)*2
//   b0 = {lo: W[k0][n],   hi: W[k0+1][n]}
//   b1 = {lo: W[k0+8][n], hi: W[k0+9][n]}
__device__ __forceinline__ void stage_w_h2(uint2* Wb, const float* __restrict__ W) {
    for (int i = threadIdx.x; i < 4096; i += blockDim.x) {
        int ks = i >> 9, nb = (i >> 5) & 15, lid = i & 31;
        int n  = nb * 8 + (lid >> 2);
        int k0 = ks * 16 + (lid & 3) * 2;
        uint2 v;
        v.x = packh2(W[(k0    ) * 128 + n], W[(k0 + 1) * 128 + n]);
        v.y = packh2(W[(k0 + 8) * 128 + n], W[(k0 + 9) * 128 + n]);
        Wb[i] = v;
    }
}

// Gather-store one row (e, lane) float4 -> fp16 tile in A-fragment order.
// pair0 = cols (4L,4L+1), pair1 = (4L+2,4L+3); ks = L>>2;
// reg = (e>>3) + ((L>>1)&1)*2 ; lane'0 = (e&7)*4 + (L&1)*2 ; lane'1 = lane'0+1
__device__ __forceinline__ void tile_store(char* tile, int e, int lane, float4 t) {
    int ks  = lane >> 2;
    int reg = (e >> 3) + ((lane >> 1) & 1) * 2;
    int lp0 = (e & 7) * 4 + (lane & 1) * 2;
    char* base = tile + ks * 528 + reg * 4;
    *(uint32_t*)(base + lp0 * 16)       = packh2(t.x, t.y);
    *(uint32_t*)(base + (lp0 + 1) * 16) = packh2(t.z, t.w);
}

// m16 x n128 x k128 fp16 mainloop: 8 ksteps x 16 nb = 128 mma16.
__device__ __forceinline__ void mma_mainloop_h(float4 acc[16], const char* tile,
                                               const uint2* Wb, int lane) {
    #pragma unroll
    for (int nb = 0; nb < 16; nb++) acc[nb] = make_float4(0.f, 0.f, 0.f, 0.f);
    #pragma unroll
    for (int ks = 0; ks < 8; ks++) {
        uint4 af = *(const uint4*)(tile + ks * 528 + lane * 16);
        const uint2* wrow = Wb + ks * 512 + lane;
        #pragma unroll
        for (int nb = 0; nb < 16; nb++) {
            uint2 Bv = wrow[nb * 32];
            mma16(acc[nb], af, Bv);
        }
    }
}

__device__ __forceinline__ void redv2(float* p, float a, float b) {
    asm volatile("red.global.add.v2.f32 [%0], {%1, %2};" :: "l"(p), "f"(a), "f"(b) : "memory");
}

// ======================= AB GEMM: A = relu_in(X)@Wa + ba ; B = relu_in(X)@Wb + bb =======================
template <bool RELU_IN>
__global__ void __launch_bounds__(TPB, 1)
ab_mma_kernel(const float* __restrict__ X, const float* __restrict__ Wa,
              const float* __restrict__ Wbm, const float* __restrict__ ba,
              const float* __restrict__ bb, float* __restrict__ Aout,
              float* __restrict__ Bout, int nrows)
{
    extern __shared__ char sm[];
    uint2* bankA = (uint2*)sm;
    uint2* bankB = (uint2*)(sm + 32768);
    const int tid = threadIdx.x, wid = tid >> 5, lane = tid & 31;
    char* tile = sm + 65536 + wid * TILE_B;

    stage_w_h2(bankA, Wa);
    stage_w_h2(bankB, Wbm);
    __syncthreads();

    const int gwarp  = blockIdx.x * 16 + wid;
    const int nwarps = gridDim.x * 16;
    const int ntasks = (nrows + 15) / 16;

    for (int task = gwarp; task < ntasks; task += nwarps) {
        const int r0 = task * 16;

        #pragma unroll 4
        for (int e = 0; e < 16; e++) {
            int r = r0 + e;
            float4 t = make_float4(0.f, 0.f, 0.f, 0.f);
            if (r < nrows) {
                t = ((const float4*)(X + (size_t)r * 128))[lane];
                if (RELU_IN) t = relu4(t);
            }
            tile_store(tile, e, lane, t);
        }
        __syncwarp();

        const int i0 = r0 + (lane >> 2);
        const int i1 = i0 + 8;
        float4 acc[16];

        // ---- A output ----
        mma_mainloop_h(acc, tile, bankA, lane);
        #pragma unroll
        for (int nb = 0; nb < 16; nb++) {
            int c = 2 * (lane & 3) + nb * 8;
            float b0 = __ldg(ba + c), b1 = __ldg(ba + c + 1);
            if (i0 < nrows)
                *(float2*)(Aout + (size_t)i0 * 128 + c) = make_float2(acc[nb].x + b0, acc[nb].y + b1);
            if (i1 < nrows)
                *(float2*)(Aout + (size_t)i1 * 128 + c) = make_float2(acc[nb].z + b0, acc[nb].w + b1);
        }

        // ---- B output ----
        mma_mainloop_h(acc, tile, bankB, lane);
        #pragma unroll
        for (int nb = 0; nb < 16; nb++) {
            int c = 2 * (lane & 3) + nb * 8;
            float b0 = __ldg(bb + c), b1 = __ldg(bb + c + 1);
            if (i0 < nrows)
                *(float2*)(Bout + (size_t)i0 * 128 + c) = make_float2(acc[nb].x + b0, acc[nb].y + b1);
            if (i1 < nrows)
                *(float2*)(Bout + (size_t)i1 * 128 + c) = make_float2(acc[nb].z + b0, acc[nb].w + b1);
        }
        __syncwarp();
    }
}

// ======================= msg GEMM: out = T @ w2 + (deg+1)*b2 =======================
template <bool POOL>
__global__ void __launch_bounds__(TPB, 1)
msg_mma_kernel(const float* __restrict__ T, const float* __restrict__ W2,
               const float* __restrict__ b2, const int* __restrict__ deg,
               const int* __restrict__ batch, float* __restrict__ agg,
               float* __restrict__ pool, int nrows)
{
    extern __shared__ char sm[];
    uint2* bankW = (uint2*)sm;
    const int tid = threadIdx.x, wid = tid >> 5, lane = tid & 31;
    char* tile = sm + 32768 + wid * TILE_B;

    stage_w_h2(bankW, W2);
    __syncthreads();

    const int gwarp  = blockIdx.x * 16 + wid;
    const int nwarps = gridDim.x * 16;
    const int ntasks = (nrows + 15) / 16;

    for (int task = gwarp; task < ntasks; task += nwarps) {
        const int r0 = task * 16;

        #pragma unroll 4
        for (int e = 0; e < 16; e++) {
            int r = r0 + e;
            float4 t = make_float4(0.f, 0.f, 0.f, 0.f);
            if (r < nrows) t = ((const float4*)(T + (size_t)r * 128))[lane];
            tile_store(tile, e, lane, t);
        }
        __syncwarp();

        float4 acc[16];
        mma_mainloop_h(acc, tile, bankW, lane);
        __syncwarp();

        int i0 = r0 + (lane >> 2);
        int i1 = i0 + 8;
        float s0 = 0.f, s1 = 0.f;
        int g0 = 0, g1 = 0;
        if (i0 < nrows) { s0 = (float)(__ldg(deg + i0) + 1); if (POOL) g0 = __ldg(batch + i0); }
        if (i1 < nrows) { s1 = (float)(__ldg(deg + i1) + 1); if (POOL) g1 = __ldg(batch + i1); }
        #pragma unroll
        for (int nb = 0; nb < 16; nb++) {
            int c = 2 * (lane & 3) + nb * 8;
            float q0 = __ldg(b2 + c), q1 = __ldg(b2 + c + 1);
            if (POOL) {
                if (i0 < nrows)
                    redv2(pool + (size_t)g0 * 128 + c,
                          fmaxf(acc[nb].x + s0 * q0, 0.f), fmaxf(acc[nb].y + s0 * q1, 0.f));
                if (i1 < nrows)
                    redv2(pool + (size_t)g1 * 128 + c,
                          fmaxf(acc[nb].z + s1 * q0, 0.f), fmaxf(acc[nb].w + s1 * q1, 0.f));
            } else {
                if (i0 < nrows)
                    *(float2*)(agg + (size_t)i0 * 128 + c) = make_float2(acc[nb].x + s0 * q0, acc[nb].y + s0 * q1);
                if (i1 < nrows)
                    *(float2*)(agg + (size_t)i1 * 128 + c) = make_float2(acc[nb].z + s1 * q0, acc[nb].w + s1 * q1);
            }
        }
    }
}

// ======================= accum (high occupancy, no smem) =======================
__global__ void __launch_bounds__(512)
accum_kernel(const float* __restrict__ A, const float* __restrict__ B,
             const int* __restrict__ ssrc, const int* __restrict__ start,
             float* __restrict__ T, int n)
{
    const int gw   = (blockIdx.x * blockDim.x + threadIdx.x) >> 5;
    const int lane = threadIdx.x & 31;
    const int nw   = (gridDim.x * blockDim.x) >> 5;

    for (int node = gw; node < n; node += nw) {
        float4 a  = ((const float4*)(A + (size_t)node * 128))[lane];
        float4 bs = ((const float4*)(B + (size_t)node * 128))[lane];
        float4 acc = relu4(make_float4(a.x + bs.x, a.y + bs.y, a.z + bs.z, a.w + bs.w)); // self loop

        int e  = __ldg(start + node);
        int e1 = __ldg(start + node + 1);
        for (; e + 4 <= e1; e += 4) {
            int j0 = __ldg(ssrc + e),     j1 = __ldg(ssrc + e + 1);
            int j2 = __ldg(ssrc + e + 2), j3 = __ldg(ssrc + e + 3);
            float4 b0 = ((const float4*)(B + (size_t)j0 * 128))[lane];
            float4 b1 = ((const float4*)(B + (size_t)j1 * 128))[lane];
            float4 b2 = ((const float4*)(B + (size_t)j2 * 128))[lane];
            float4 b3 = ((const float4*)(B + (size_t)j3 * 128))[lane];
            float4 t0 = relu4(make_float4(a.x + b0.x, a.y + b0.y, a.z + b0.z, a.w + b0.w));
            float4 t1 = relu4(make_float4(a.x + b1.x, a.y + b1.y, a.z + b1.z, a.w + b1.w));
            float4 t2 = relu4(make_float4(a.x + b2.x, a.y + b2.y, a.z + b2.z, a.w + b2.w));
            float4 t3 = relu4(make_float4(a.x + b3.x, a.y + b3.y, a.z + b3.z, a.w + b3.w));
            acc.x += t0.x + t1.x + t2.x + t3.x;
            acc.y += t0.y + t1.y + t2.y + t3.y;
            acc.z += t0.z + t1.z + t2.z + t3.z;
            acc.w += t0.w + t1.w + t2.w + t3.w;
        }
        for (; e < e1; e++) {
            int j = __ldg(ssrc + e);
            float4 b = ((const float4*)(B + (size_t)j * 128))[lane];
            float4 t = relu4(make_float4(a.x + b.x, a.y + b.y, a.z + b.z, a.w + b.w));
            acc.x += t.x; acc.y += t.y; acc.z += t.z; acc.w += t.w;
        }
        ((float4*)(T + (size_t)node * 128))[lane] = acc;
    }
}

// ======================= weight composition (fp32 exact, once per launch) =======================
__global__ void compose_kernel(const float* __restrict__ Wlin, const float* __restrict__ w1p,
                               float* __restrict__ out)
{
    __shared__ float row[128];
    int k = blockIdx.x, m = threadIdx.x;
    row[m] = Wlin[k * 128 + m];
    __syncthreads();
    float s = 0.f;
    #pragma unroll 8
    for (int n = 0; n < 128; n++) s += row[n] * w1p[n * 128 + m];
    out[k * 128 + m] = s;
}

__global__ void bias_compose_kernel(const float* __restrict__ lin_b, const float* __restrict__ w1p,
                                    const float* __restrict__ b1, float* __restrict__ out)
{
    int m = threadIdx.x;
    float s = b1 ? b1[m] : 0.f;
    #pragma unroll 8
    for (int n = 0; n < 128; n++) s += lin_b[n] * w1p[n * 128 + m];
    out[m] = s;
}

// ======================= CSR / counts / final =======================
__global__ void deg_kernel(const int* __restrict__ dst, int* __restrict__ deg, int E) {
    int i = blockIdx.x * blockDim.x + threadIdx.x;
    if (i < E) atomicAdd(&deg[dst[i]], 1);
}

__global__ void cnt_kernel(const int* __restrict__ batch, float* __restrict__ cnt, int n) {
    int i = blockIdx.x * blockDim.x + threadIdx.x;
    if (i < n) atomicAdd(&cnt[batch[i]], 1.f);
}

__global__ void scan_kernel(const int* __restrict__ deg, int* __restrict__ start,
                            int* __restrict__ cursor, int n)
{
    __shared__ int carry;
    __shared__ int wsum[32];
    const int tidx = threadIdx.x, lane = tidx & 31, wid = tidx >> 5;
    if (tidx == 0) carry = 0;
    __syncthreads();

    for (int base = 0; base < n; base += 1024) {
        int i = base + tidx;
        int v = (i < n) ? deg[i] : 0;
        int x = v;
        #pragma unroll
        for (int o = 1; o < 32; o <<= 1) {
            int y = __shfl_up_sync(0xffffffffu, x, o);
            if (lane >= o) x += y;
        }
        if (lane == 31) wsum[wid] = x;
        __syncthreads();
        if (wid == 0) {
            int w = wsum[lane];
            #pragma unroll
            for (int o = 1; o < 32; o <<= 1) {
                int y = __shfl_up_sync(0xffffffffu, w, o);
                if (lane >= o) w += y;
            }
            wsum[lane] = w;
        }
        __syncthreads();
        int excl = x - v + (wid > 0 ? wsum[wid - 1] : 0) + carry;
        if (i < n) { start[i] = excl; cursor[i] = excl; }
        int blocktot = wsum[31];
        __syncthreads();
        if (tidx == 0) carry += blocktot;
        __syncthreads();
    }
    if (tidx == 0) start[n] = carry;
}

__global__ void scatter_kernel(const int* __restrict__ src, const int* __restrict__ dst,
                               int* __restrict__ cursor, int* __restrict__ ssrc, int E)
{
    int i = blockIdx.x * blockDim.x + threadIdx.x;
    if (i < E) {
        int p = atomicAdd(&cursor[dst[i]], 1);
        ssrc[p] = src[i];
    }
}

__global__ void final_kernel(const float* __restrict__ pool, const float* __restrict__ cnt,
                             const float* __restrict__ W, const float* __restrict__ b,
                             float* __restrict__ out)
{
    __shared__ float p[128];
    int g = blockIdx.x;
    float c = fmaxf(cnt[g], 1.f);
    for (int j = threadIdx.x; j < 128; j += blockDim.x)
        p[j] = pool[(size_t)g * 128 + j] / c;
    __syncthreads();
    int o = threadIdx.x;
    float s = b[o];
    #pragma unroll 4
    for (int j = 0; j < 128; j++) s += p[j] * W[j * 64 + o];
    out[(size_t)g * 64 + o] = s;
}

// ======================= launch =======================
extern "C" void kernel_launch(void* const* d_in, const int* in_sizes, int n_in,
                              void* d_out, int out_size)
{
    const float* x     = (const float*)d_in[0];
    const int*   ei    = (const int*)  d_in[1];
    const int*   batch = (const int*)  d_in[3];
    const int N = in_sizes[0] / 128;
    const int E = in_sizes[1] / 2;
    const int* src = ei;
    const int* dst = ei + E;

    const float* lin_w[3] = { (const float*)d_in[4],  (const float*)d_in[10], (const float*)d_in[16] };
    const float* lin_b[3] = { (const float*)d_in[5],  (const float*)d_in[11], (const float*)d_in[17] };
    const float* w1[3]    = { (const float*)d_in[6],  (const float*)d_in[12], (const float*)d_in[18] };
    const float* b1[3]    = { (const float*)d_in[7],  (const float*)d_in[13], (const float*)d_in[19] };
    const float* w2[3]    = { (const float*)d_in[8],  (const float*)d_in[14], (const float*)d_in[20] };
    const float* b2[3]    = { (const float*)d_in[9],  (const float*)d_in[15], (const float*)d_in[21] };
    const float* out_w    = (const float*)d_in[22];
    const float* out_b    = (const float*)d_in[23];
    float* out = (float*)d_out;

    float *A_, *B_, *T_, *agg_, *pool_, *cnt_, *Wc_, *bc_;
    int *deg_, *start_, *cursor_, *ssrc_;
    cudaGetSymbolAddress((void**)&A_,     g_A);
    cudaGetSymbolAddress((void**)&B_,     g_B);
    cudaGetSymbolAddress((void**)&T_,     g_T);
    cudaGetSymbolAddress((void**)&agg_,   g_agg);
    cudaGetSymbolAddress((void**)&pool_,  g_pool);
    cudaGetSymbolAddress((void**)&cnt_,   g_cnt);
    cudaGetSymbolAddress((void**)&deg_,   g_deg);
    cudaGetSymbolAddress((void**)&start_, g_start);
    cudaGetSymbolAddress((void**)&cursor_,g_cursor);
    cudaGetSymbolAddress((void**)&ssrc_,  g_ssrc);
    cudaGetSymbolAddress((void**)&Wc_,    g_Wc);
    cudaGetSymbolAddress((void**)&bc_,    g_bc);

    cudaFuncSetAttribute((const void*)ab_mma_kernel<false>,
                         cudaFuncAttributeMaxDynamicSharedMemorySize, AB_SMEM);
    cudaFuncSetAttribute((const void*)ab_mma_kernel<true>,
                         cudaFuncAttributeMaxDynamicSharedMemorySize, AB_SMEM);
    cudaFuncSetAttribute((const void*)msg_mma_kernel<false>,
                         cudaFuncAttributeMaxDynamicSharedMemorySize, MSG_SMEM);
    cudaFuncSetAttribute((const void*)msg_mma_kernel<true>,
                         cudaFuncAttributeMaxDynamicSharedMemorySize, MSG_SMEM);

    const int G = out_size / 64;

    // ---- prep: CSR by dst, counts, composite weights ----
    cudaMemsetAsync(deg_,  0, (size_t)N * sizeof(int));
    cudaMemsetAsync(pool_, 0, (size_t)G * 128 * sizeof(float));
    cudaMemsetAsync(cnt_,  0, (size_t)G * sizeof(float));
    deg_kernel<<<(E + 255) / 256, 256>>>(dst, deg_, E);
    cnt_kernel<<<(N + 255) / 256, 256>>>(batch, cnt_, N);
    scan_kernel<<<1, 1024>>>(deg_, start_, cursor_, N);
    scatter_kernel<<<(E + 255) / 256, 256>>>(src, dst, cursor_, ssrc_, E);
    for (int l = 0; l < 3; l++) {
        const float* w1t = w1[l];
        const float* w1b = w1[l] + 128 * 128;
        compose_kernel<<<128, 128>>>(lin_w[l], w1t, Wc_ + (2 * l    ) * 16384);
        compose_kernel<<<128, 128>>>(lin_w[l], w1b, Wc_ + (2 * l + 1) * 16384);
        bias_compose_kernel<<<1, 128>>>(lin_b[l], w1t, b1[l],  bc_ + (2 * l    ) * 128);
        bias_compose_kernel<<<1, 128>>>(lin_b[l], w1b, nullptr, bc_ + (2 * l + 1) * 128);
    }

    for (int l = 0; l < 3; l++) {
        const float* X  = (l == 0) ? x : agg_;
        const float* Wa = Wc_ + (2 * l    ) * 16384;
        const float* Wb = Wc_ + (2 * l + 1) * 16384;
        const float* ba = bc_ + (2 * l    ) * 128;
        const float* bb = bc_ + (2 * l + 1) * 128;
        if (l == 0)
            ab_mma_kernel<false><<<NBLK, TPB, AB_SMEM>>>(X, Wa, Wb, ba, bb, A_, B_, N);
        else
            ab_mma_kernel<true ><<<NBLK, TPB, AB_SMEM>>>(X, Wa, Wb, ba, bb, A_, B_, N);
        accum_kernel<<<296, 512>>>(A_, B_, ssrc_, start_, T_, N);
        if (l < 2)
            msg_mma_kernel<false><<<NBLK, TPB, MSG_SMEM>>>(T_, w2[l], b2[l], deg_, batch, agg_, pool_, N);
        else
            msg_mma_kernel<true ><<<NBLK, TPB, MSG_SMEM>>>(T_, w2[l], b2[l], deg_, batch, agg_, pool_, N);
    }

    final_kernel<<<G, 64>>>(pool_, cnt_, out_w, out_b, out);
}

// round 15
// speedup vs baseline: 2.3515x; 1.0401x over previous
#include <cuda_runtime.h>
#include <cuda_fp16.h>
#include <cstdint>

#define NBLK    148
#define TPB     512
#define TILE_B  (8*528)                            // 4224 bytes per warp tile (fp16)
#define MSG_SMEM (32768 + 16*TILE_B)               // 100352 B
#define AB_SMEM  (65536 + 16*TILE_B)               // 133120 B

// Scratch (device globals: allocation-free rule)
__device__ float    g_A   [50000 * 128];
__device__ uint32_t g_Bh  [50000 * 64];            // B packed fp16
__device__ uint32_t g_Th  [50000 * 64];            // T packed fp16
__device__ uint32_t g_aggh[50000 * 64];            // relu(agg) packed fp16
__device__ float    g_pool[64 * 128];
__device__ float    g_cnt [64];
__device__ int      g_deg [50000];
__device__ int      g_start[50001];
__device__ int      g_cursor[50000];
__device__ int      g_ssrc[800000];
__device__ float    g_Wc  [6 * 16384];             // composite Wa/Wb per layer (fp32)
__device__ float    g_bc  [6 * 128];               // composite biases

__device__ __forceinline__ float4 relu4(float4 v) {
    v.x = fmaxf(v.x, 0.f); v.y = fmaxf(v.y, 0.f);
    v.z = fmaxf(v.z, 0.f); v.w = fmaxf(v.w, 0.f);
    return v;
}

// ======================= fp16 helpers =======================
// pack: d[15:0] = lo, d[31:16] = hi
__device__ __forceinline__ uint32_t packh2(float lo, float hi) {
    uint32_t r;
    asm("cvt.rn.f16x2.f32 %0, %1, %2;" : "=r"(r) : "f"(hi), "f"(lo));
    return r;
}
__device__ __forceinline__ float2 unpackh2(uint32_t v) {
    __half2 h = *(__half2*)&v;
    return __half22float2(h);
}
__device__ __forceinline__ void mma16(float4 &d, uint4 a, uint2 b) {
    asm volatile("mma.sync.aligned.m16n8k16.row.col.f32.f16.f16.f32 "
        "{%0,%1,%2,%3}, {%4,%5,%6,%7}, {%8,%9}, {%0,%1,%2,%3};"
        : "+f"(d.x), "+f"(d.y), "+f"(d.z), "+f"(d.w)
        : "r"(a.x), "r"(a.y), "r"(a.z), "r"(a.w), "r"(b.x), "r"(b.y));
}

// Stage W (row-major [k][n], 128x128, fp32) into fp16 B-fragment bank (32 KB).
__device__ __forceinline__ void stage_w_h2(uint2* Wb, const float* __restrict__ W) {
    for (int i = threadIdx.x; i < 4096; i += blockDim.x) {
        int ks = i >> 9, nb = (i >> 5) & 15, lid = i & 31;
        int n  = nb * 8 + (lid >> 2);
        int k0 = ks * 16 + (lid & 3) * 2;
        uint2 v;
        v.x = packh2(W[(k0    ) * 128 + n], W[(k0 + 1) * 128 + n]);
        v.y = packh2(W[(k0 + 8) * 128 + n], W[(k0 + 9) * 128 + n]);
        Wb[i] = v;
    }
}

// Tile store from fp32 float4 (cols 4L..4L+3 of row e)
__device__ __forceinline__ void tile_store_f4(char* tile, int e, int lane, float4 t) {
    int ks  = lane >> 2;
    int reg = (e >> 3) + ((lane >> 1) & 1) * 2;
    int lp0 = (e & 7) * 4 + (lane & 1) * 2;
    char* base = tile + ks * 528 + reg * 4;
    *(uint32_t*)(base + lp0 * 16)       = packh2(t.x, t.y);
    *(uint32_t*)(base + (lp0 + 1) * 16) = packh2(t.z, t.w);
}
// Tile store from pre-packed fp16 (u0 = cols 4L,4L+1; u1 = 4L+2,4L+3)
__device__ __forceinline__ void tile_store_h2(char* tile, int e, int lane, uint32_t u0, uint32_t u1) {
    int ks  = lane >> 2;
    int reg = (e >> 3) + ((lane >> 1) & 1) * 2;
    int lp0 = (e & 7) * 4 + (lane & 1) * 2;
    char* base = tile + ks * 528 + reg * 4;
    *(uint32_t*)(base + lp0 * 16)       = u0;
    *(uint32_t*)(base + (lp0 + 1) * 16) = u1;
}

// m16 x n128 x k128 fp16 mainloop: 128 mma16.
__device__ __forceinline__ void mma_mainloop_h(float4 acc[16], const char* tile,
                                               const uint2* Wb, int lane) {
    #pragma unroll
    for (int nb = 0; nb < 16; nb++) acc[nb] = make_float4(0.f, 0.f, 0.f, 0.f);
    #pragma unroll
    for (int ks = 0; ks < 8; ks++) {
        uint4 af = *(const uint4*)(tile + ks * 528 + lane * 16);
        const uint2* wrow = Wb + ks * 512 + lane;
        #pragma unroll
        for (int nb = 0; nb < 16; nb++) {
            uint2 Bv = wrow[nb * 32];
            mma16(acc[nb], af, Bv);
        }
    }
}

__device__ __forceinline__ void redv2(float* p, float a, float b) {
    asm volatile("red.global.add.v2.f32 [%0], {%1, %2};" :: "l"(p), "f"(a), "f"(b) : "memory");
}

// ======================= AB GEMM: A = X@Wa + ba (fp32) ; B = X@Wb + bb (fp16) =======================
// H16IN: X is packed-fp16, already relu'd (inter-layer). Else fp32 raw input.
template <bool H16IN>
__global__ void __launch_bounds__(TPB, 1)
ab_mma_kernel(const void* __restrict__ Xv, const float* __restrict__ Wa,
              const float* __restrict__ Wbm, const float* __restrict__ ba,
              const float* __restrict__ bb, float* __restrict__ Aout,
              uint32_t* __restrict__ Bout, int nrows)
{
    extern __shared__ char sm[];
    uint2* bankA = (uint2*)sm;
    uint2* bankB = (uint2*)(sm + 32768);
    const int tid = threadIdx.x, wid = tid >> 5, lane = tid & 31;
    char* tile = sm + 65536 + wid * TILE_B;

    stage_w_h2(bankA, Wa);
    stage_w_h2(bankB, Wbm);
    __syncthreads();

    const int gwarp  = blockIdx.x * 16 + wid;
    const int nwarps = gridDim.x * 16;
    const int ntasks = (nrows + 15) / 16;

    for (int task = gwarp; task < ntasks; task += nwarps) {
        const int r0 = task * 16;

        #pragma unroll 4
        for (int e = 0; e < 16; e++) {
            int r = r0 + e;
            if (H16IN) {
                uint2 v = make_uint2(0u, 0u);
                if (r < nrows) v = ((const uint2*)Xv)[r * 32 + lane];
                tile_store_h2(tile, e, lane, v.x, v.y);
            } else {
                float4 t = make_float4(0.f, 0.f, 0.f, 0.f);
                if (r < nrows) t = ((const float4*)Xv)[r * 32 + lane];
                tile_store_f4(tile, e, lane, t);
            }
        }
        __syncwarp();

        const int i0 = r0 + (lane >> 2);
        const int i1 = i0 + 8;
        float4 acc[16];

        // ---- A output (fp32) ----
        mma_mainloop_h(acc, tile, bankA, lane);
        #pragma unroll
        for (int nb = 0; nb < 16; nb++) {
            int c = 2 * (lane & 3) + nb * 8;
            float b0 = __ldg(ba + c), b1 = __ldg(ba + c + 1);
            if (i0 < nrows)
                *(float2*)(Aout + (size_t)i0 * 128 + c) = make_float2(acc[nb].x + b0, acc[nb].y + b1);
            if (i1 < nrows)
                *(float2*)(Aout + (size_t)i1 * 128 + c) = make_float2(acc[nb].z + b0, acc[nb].w + b1);
        }

        // ---- B output (fp16 packed) ----
        mma_mainloop_h(acc, tile, bankB, lane);
        #pragma unroll
        for (int nb = 0; nb < 16; nb++) {
            int c = 2 * (lane & 3) + nb * 8;
            float b0 = __ldg(bb + c), b1 = __ldg(bb + c + 1);
            if (i0 < nrows)
                Bout[(size_t)i0 * 64 + (c >> 1)] = packh2(acc[nb].x + b0, acc[nb].y + b1);
            if (i1 < nrows)
                Bout[(size_t)i1 * 64 + (c >> 1)] = packh2(acc[nb].z + b0, acc[nb].w + b1);
        }
        __syncwarp();
    }
}

// ======================= msg GEMM: out = T @ w2 + (deg+1)*b2 =======================
// POOL: relu + mean-pool atomics into pool[batch]; else relu + pack fp16 into agg16.
template <bool POOL>
__global__ void __launch_bounds__(TPB, 1)
msg_mma_kernel(const uint32_t* __restrict__ Th, const float* __restrict__ W2,
               const float* __restrict__ b2, const int* __restrict__ deg,
               const int* __restrict__ batch, uint32_t* __restrict__ agg16,
               float* __restrict__ pool, int nrows)
{
    extern __shared__ char sm[];
    uint2* bankW = (uint2*)sm;
    const int tid = threadIdx.x, wid = tid >> 5, lane = tid & 31;
    char* tile = sm + 32768 + wid * TILE_B;

    stage_w_h2(bankW, W2);
    __syncthreads();

    const int gwarp  = blockIdx.x * 16 + wid;
    const int nwarps = gridDim.x * 16;
    const int ntasks = (nrows + 15) / 16;

    for (int task = gwarp; task < ntasks; task += nwarps) {
        const int r0 = task * 16;

        #pragma unroll 4
        for (int e = 0; e < 16; e++) {
            int r = r0 + e;
            uint2 v = make_uint2(0u, 0u);
            if (r < nrows) v = ((const uint2*)Th)[r * 32 + lane];
            tile_store_h2(tile, e, lane, v.x, v.y);
        }
        __syncwarp();

        float4 acc[16];
        mma_mainloop_h(acc, tile, bankW, lane);
        __syncwarp();

        int i0 = r0 + (lane >> 2);
        int i1 = i0 + 8;
        float s0 = 0.f, s1 = 0.f;
        int g0 = 0, g1 = 0;
        if (i0 < nrows) { s0 = (float)(__ldg(deg + i0) + 1); if (POOL) g0 = __ldg(batch + i0); }
        if (i1 < nrows) { s1 = (float)(__ldg(deg + i1) + 1); if (POOL) g1 = __ldg(batch + i1); }
        #pragma unroll
        for (int nb = 0; nb < 16; nb++) {
            int c = 2 * (lane & 3) + nb * 8;
            float q0 = __ldg(b2 + c), q1 = __ldg(b2 + c + 1);
            float v0x = fmaxf(acc[nb].x + s0 * q0, 0.f), v0y = fmaxf(acc[nb].y + s0 * q1, 0.f);
            float v1x = fmaxf(acc[nb].z + s1 * q0, 0.f), v1y = fmaxf(acc[nb].w + s1 * q1, 0.f);
            if (POOL) {
                if (i0 < nrows) redv2(pool + (size_t)g0 * 128 + c, v0x, v0y);
                if (i1 < nrows) redv2(pool + (size_t)g1 * 128 + c, v1x, v1y);
            } else {
                if (i0 < nrows) agg16[(size_t)i0 * 64 + (c >> 1)] = packh2(v0x, v0y);
                if (i1 < nrows) agg16[(size_t)i1 * 64 + (c >> 1)] = packh2(v1x, v1y);
            }
        }
    }
}

// ======================= accum (high occupancy, no smem) =======================
// T[n] = relu(A[n]+B[n]) + sum_{e in CSR[n]} relu(A[n]+B[ssrc[e]]) ; T packed fp16.
__global__ void __launch_bounds__(512)
accum_kernel(const float* __restrict__ A, const uint32_t* __restrict__ Bh,
             const int* __restrict__ ssrc, const int* __restrict__ start,
             uint32_t* __restrict__ Th, int n)
{
    const int gw   = (blockIdx.x * blockDim.x + threadIdx.x) >> 5;
    const int lane = threadIdx.x & 31;
    const int nw   = (gridDim.x * blockDim.x) >> 5;

    for (int node = gw; node < n; node += nw) {
        float4 a = ((const float4*)(A + (size_t)node * 128))[lane];
        uint2 vs = ((const uint2*)Bh)[node * 32 + lane];
        float2 s0 = unpackh2(vs.x), s1 = unpackh2(vs.y);
        float4 acc = relu4(make_float4(a.x + s0.x, a.y + s0.y, a.z + s1.x, a.w + s1.y)); // self loop

        int e  = __ldg(start + node);
        int e1 = __ldg(start + node + 1);
        for (; e + 4 <= e1; e += 4) {
            int j0 = __ldg(ssrc + e),     j1 = __ldg(ssrc + e + 1);
            int j2 = __ldg(ssrc + e + 2), j3 = __ldg(ssrc + e + 3);
            uint2 v0 = ((const uint2*)Bh)[j0 * 32 + lane];
            uint2 v1 = ((const uint2*)Bh)[j1 * 32 + lane];
            uint2 v2 = ((const uint2*)Bh)[j2 * 32 + lane];
            uint2 v3 = ((const uint2*)Bh)[j3 * 32 + lane];
            float2 p0a = unpackh2(v0.x), p0b = unpackh2(v0.y);
            float2 p1a = unpackh2(v1.x), p1b = unpackh2(v1.y);
            float2 p2a = unpackh2(v2.x), p2b = unpackh2(v2.y);
            float2 p3a = unpackh2(v3.x), p3b = unpackh2(v3.y);
            float4 t0 = relu4(make_float4(a.x + p0a.x, a.y + p0a.y, a.z + p0b.x, a.w + p0b.y));
            float4 t1 = relu4(make_float4(a.x + p1a.x, a.y + p1a.y, a.z + p1b.x, a.w + p1b.y));
            float4 t2 = relu4(make_float4(a.x + p2a.x, a.y + p2a.y, a.z + p2b.x, a.w + p2b.y));
            float4 t3 = relu4(make_float4(a.x + p3a.x, a.y + p3a.y, a.z + p3b.x, a.w + p3b.y));
            acc.x += t0.x + t1.x + t2.x + t3.x;
            acc.y += t0.y + t1.y + t2.y + t3.y;
            acc.z += t0.z + t1.z + t2.z + t3.z;
            acc.w += t0.w + t1.w + t2.w + t3.w;
        }
        for (; e < e1; e++) {
            int j = __ldg(ssrc + e);
            uint2 v = ((const uint2*)Bh)[j * 32 + lane];
            float2 pa = unpackh2(v.x), pb = unpackh2(v.y);
            float4 t = relu4(make_float4(a.x + pa.x, a.y + pa.y, a.z + pb.x, a.w + pb.y));
            acc.x += t.x; acc.y += t.y; acc.z += t.z; acc.w += t.w;
        }
        ((uint2*)Th)[node * 32 + lane] = make_uint2(packh2(acc.x, acc.y), packh2(acc.z, acc.w));
    }
}

// ======================= weight composition (fp32 exact, once per launch) =======================
__global__ void compose_kernel(const float* __restrict__ Wlin, const float* __restrict__ w1p,
                               float* __restrict__ out)
{
    __shared__ float row[128];
    int k = blockIdx.x, m = threadIdx.x;
    row[m] = Wlin[k * 128 + m];
    __syncthreads();
    float s = 0.f;
    #pragma unroll 8
    for (int n = 0; n < 128; n++) s += row[n] * w1p[n * 128 + m];
    out[k * 128 + m] = s;
}

__global__ void bias_compose_kernel(const float* __restrict__ lin_b, const float* __restrict__ w1p,
                                    const float* __restrict__ b1, float* __restrict__ out)
{
    int m = threadIdx.x;
    float s = b1 ? b1[m] : 0.f;
    #pragma unroll 8
    for (int n = 0; n < 128; n++) s += lin_b[n] * w1p[n * 128 + m];
    out[m] = s;
}

// ======================= CSR / counts / final =======================
__global__ void degcnt_kernel(const int* __restrict__ dst, const int* __restrict__ batch,
                              int* __restrict__ deg, float* __restrict__ cnt, int E, int n)
{
    int i = blockIdx.x * blockDim.x + threadIdx.x;
    if (i < E) atomicAdd(&deg[dst[i]], 1);
    if (i < n) atomicAdd(&cnt[batch[i]], 1.f);
}

__global__ void scan_kernel(const int* __restrict__ deg, int* __restrict__ start,
                            int* __restrict__ cursor, int n)
{
    __shared__ int carry;
    __shared__ int wsum[32];
    const int tidx = threadIdx.x, lane = tidx & 31, wid = tidx >> 5;
    if (tidx == 0) carry = 0;
    __syncthreads();

    for (int base = 0; base < n; base += 1024) {
        int i = base + tidx;
        int v = (i < n) ? deg[i] : 0;
        int x = v;
        #pragma unroll
        for (int o = 1; o < 32; o <<= 1) {
            int y = __shfl_up_sync(0xffffffffu, x, o);
            if (lane >= o) x += y;
        }
        if (lane == 31) wsum[wid] = x;
        __syncthreads();
        if (wid == 0) {
            int w = wsum[lane];
            #pragma unroll
            for (int o = 1; o < 32; o <<= 1) {
                int y = __shfl_up_sync(0xffffffffu, w, o);
                if (lane >= o) w += y;
            }
            wsum[lane] = w;
        }
        __syncthreads();
        int excl = x - v + (wid > 0 ? wsum[wid - 1] : 0) + carry;
        if (i < n) { start[i] = excl; cursor[i] = excl; }
        int blocktot = wsum[31];
        __syncthreads();
        if (tidx == 0) carry += blocktot;
        __syncthreads();
    }
    if (tidx == 0) start[n] = carry;
}

__global__ void scatter_kernel(const int* __restrict__ src, const int* __restrict__ dst,
                               int* __restrict__ cursor, int* __restrict__ ssrc, int E)
{
    int i = blockIdx.x * blockDim.x + threadIdx.x;
    if (i < E) {
        int p = atomicAdd(&cursor[dst[i]], 1);
        ssrc[p] = src[i];
    }
}

__global__ void final_kernel(const float* __restrict__ pool, const float* __restrict__ cnt,
                             const float* __restrict__ W, const float* __restrict__ b,
                             float* __restrict__ out)
{
    __shared__ float p[128];
    int g = blockIdx.x;
    float c = fmaxf(cnt[g], 1.f);
    for (int j = threadIdx.x; j < 128; j += blockDim.x)
        p[j] = pool[(size_t)g * 128 + j] / c;
    __syncthreads();
    int o = threadIdx.x;
    float s = b[o];
    #pragma unroll 4
    for (int j = 0; j < 128; j++) s += p[j] * W[j * 64 + o];
    out[(size_t)g * 64 + o] = s;
}

// ======================= launch =======================
extern "C" void kernel_launch(void* const* d_in, const int* in_sizes, int n_in,
                              void* d_out, int out_size)
{
    const float* x     = (const float*)d_in[0];
    const int*   ei    = (const int*)  d_in[1];
    const int*   batch = (const int*)  d_in[3];
    const int N = in_sizes[0] / 128;
    const int E = in_sizes[1] / 2;
    const int* src = ei;
    const int* dst = ei + E;

    const float* lin_w[3] = { (const float*)d_in[4],  (const float*)d_in[10], (const float*)d_in[16] };
    const float* lin_b[3] = { (const float*)d_in[5],  (const float*)d_in[11], (const float*)d_in[17] };
    const float* w1[3]    = { (const float*)d_in[6],  (const float*)d_in[12], (const float*)d_in[18] };
    const float* b1[3]    = { (const float*)d_in[7],  (const float*)d_in[13], (const float*)d_in[19] };
    const float* w2[3]    = { (const float*)d_in[8],  (const float*)d_in[14], (const float*)d_in[20] };
    const float* b2[3]    = { (const float*)d_in[9],  (const float*)d_in[15], (const float*)d_in[21] };
    const float* out_w    = (const float*)d_in[22];
    const float* out_b    = (const float*)d_in[23];
    float* out = (float*)d_out;

    float *A_, *pool_, *cnt_, *Wc_, *bc_;
    uint32_t *Bh_, *Th_, *aggh_;
    int *deg_, *start_, *cursor_, *ssrc_;
    cudaGetSymbolAddress((void**)&A_,     g_A);
    cudaGetSymbolAddress((void**)&Bh_,    g_Bh);
    cudaGetSymbolAddress((void**)&Th_,    g_Th);
    cudaGetSymbolAddress((void**)&aggh_,  g_aggh);
    cudaGetSymbolAddress((void**)&pool_,  g_pool);
    cudaGetSymbolAddress((void**)&cnt_,   g_cnt);
    cudaGetSymbolAddress((void**)&deg_,   g_deg);
    cudaGetSymbolAddress((void**)&start_, g_start);
    cudaGetSymbolAddress((void**)&cursor_,g_cursor);
    cudaGetSymbolAddress((void**)&ssrc_,  g_ssrc);
    cudaGetSymbolAddress((void**)&Wc_,    g_Wc);
    cudaGetSymbolAddress((void**)&bc_,    g_bc);

    cudaFuncSetAttribute((const void*)ab_mma_kernel<false>,
                         cudaFuncAttributeMaxDynamicSharedMemorySize, AB_SMEM);
    cudaFuncSetAttribute((const void*)ab_mma_kernel<true>,
                         cudaFuncAttributeMaxDynamicSharedMemorySize, AB_SMEM);
    cudaFuncSetAttribute((const void*)msg_mma_kernel<false>,
                         cudaFuncAttributeMaxDynamicSharedMemorySize, MSG_SMEM);
    cudaFuncSetAttribute((const void*)msg_mma_kernel<true>,
                         cudaFuncAttributeMaxDynamicSharedMemorySize, MSG_SMEM);

    const int G = out_size / 64;

    // ---- prep: CSR by dst, counts, composite weights ----
    cudaMemsetAsync(deg_,  0, (size_t)N * sizeof(int));
    cudaMemsetAsync(pool_, 0, (size_t)G * 128 * sizeof(float));
    cudaMemsetAsync(cnt_,  0, (size_t)G * sizeof(float));
    degcnt_kernel<<<(E + 255) / 256, 256>>>(dst, batch, deg_, cnt_, E, N);
    scan_kernel<<<1, 1024>>>(deg_, start_, cursor_, N);
    scatter_kernel<<<(E + 255) / 256, 256>>>(src, dst, cursor_, ssrc_, E);
    for (int l = 0; l < 3; l++) {
        const float* w1t = w1[l];
        const float* w1b = w1[l] + 128 * 128;
        compose_kernel<<<128, 128>>>(lin_w[l], w1t, Wc_ + (2 * l    ) * 16384);
        compose_kernel<<<128, 128>>>(lin_w[l], w1b, Wc_ + (2 * l + 1) * 16384);
        bias_compose_kernel<<<1, 128>>>(lin_b[l], w1t, b1[l],  bc_ + (2 * l    ) * 128);
        bias_compose_kernel<<<1, 128>>>(lin_b[l], w1b, nullptr, bc_ + (2 * l + 1) * 128);
    }

    for (int l = 0; l < 3; l++) {
        const float* Wa = Wc_ + (2 * l    ) * 16384;
        const float* Wb = Wc_ + (2 * l + 1) * 16384;
        const float* ba = bc_ + (2 * l    ) * 128;
        const float* bb = bc_ + (2 * l + 1) * 128;
        if (l == 0)
            ab_mma_kernel<false><<<NBLK, TPB, AB_SMEM>>>(x, Wa, Wb, ba, bb, A_, Bh_, N);
        else
            ab_mma_kernel<true ><<<NBLK, TPB, AB_SMEM>>>(aggh_, Wa, Wb, ba, bb, A_, Bh_, N);
        accum_kernel<<<296, 512>>>(A_, Bh_, ssrc_, start_, Th_, N);
        if (l < 2)
            msg_mma_kernel<false><<<NBLK, TPB, MSG_SMEM>>>(Th_, w2[l], b2[l], deg_, batch, aggh_, pool_, N);
        else
            msg_mma_kernel<true ><<<NBLK, TPB, MSG_SMEM>>>(Th_, w2[l], b2[l], deg_, batch, aggh_, pool_, N);
    }

    final_kernel<<<G, 64>>>(pool_, cnt_, out_w, out_b, out);
}

// round 17
// speedup vs baseline: 2.7492x; 1.1691x over previous
#include <cuda_runtime.h>
#include <cuda_fp16.h>
#include <cstdint>

#define NBLK    148
#define TPB     512
#define TILE_B  (8*528)                            // 4224 bytes per warp tile (fp16)
#define MSG_SMEM (32768 + 16*TILE_B)               // 100352 B
#define AB_SMEM  (65536 + 16*TILE_B)               // 133120 B

// Scratch (device globals: allocation-free rule)
__device__ float    g_A   [50000 * 128];
__device__ uint32_t g_Bh  [50000 * 64];            // B packed fp16
__device__ uint32_t g_Th  [50000 * 64];            // T packed fp16
__device__ uint32_t g_aggh[50000 * 64];            // relu(agg) packed fp16
__device__ float    g_pool[64 * 128];
__device__ float    g_cnt [64];
__device__ int      g_deg [50000];
__device__ int      g_start[50001];
__device__ int      g_cursor[50000];
__device__ int      g_ssrc[800000];
__device__ float    g_Wc  [6 * 16384];             // composite Wa/Wb per layer (fp32)
__device__ float    g_bc  [6 * 128];               // composite biases

__device__ __forceinline__ float4 relu4(float4 v) {
    v.x = fmaxf(v.x, 0.f); v.y = fmaxf(v.y, 0.f);
    v.z = fmaxf(v.z, 0.f); v.w = fmaxf(v.w, 0.f);
    return v;
}

// ======================= fp16 helpers =======================
// pack: d[15:0] = lo, d[31:16] = hi
__device__ __forceinline__ uint32_t packh2(float lo, float hi) {
    uint32_t r;
    asm("cvt.rn.f16x2.f32 %0, %1, %2;" : "=r"(r) : "f"(hi), "f"(lo));
    return r;
}
__device__ __forceinline__ float2 unpackh2(uint32_t v) {
    __half2 h = *(__half2*)&v;
    return __half22float2(h);
}
__device__ __forceinline__ void mma16(float4 &d, uint4 a, uint2 b) {
    asm volatile("mma.sync.aligned.m16n8k16.row.col.f32.f16.f16.f32 "
        "{%0,%1,%2,%3}, {%4,%5,%6,%7}, {%8,%9}, {%0,%1,%2,%3};"
        : "+f"(d.x), "+f"(d.y), "+f"(d.z), "+f"(d.w)
        : "r"(a.x), "r"(a.y), "r"(a.z), "r"(a.w), "r"(b.x), "r"(b.y));
}

// Stage W (row-major [k][n], 128x128, fp32) into fp16 B-fragment bank (32 KB).
__device__ __forceinline__ void stage_w_h2(uint2* Wb, const float* __restrict__ W) {
    for (int i = threadIdx.x; i < 4096; i += blockDim.x) {
        int ks = i >> 9, nb = (i >> 5) & 15, lid = i & 31;
        int n  = nb * 8 + (lid >> 2);
        int k0 = ks * 16 + (lid & 3) * 2;
        uint2 v;
        v.x = packh2(W[(k0    ) * 128 + n], W[(k0 + 1) * 128 + n]);
        v.y = packh2(W[(k0 + 8) * 128 + n], W[(k0 + 9) * 128 + n]);
        Wb[i] = v;
    }
}

// Tile store from fp32 float4 (cols 4L..4L+3 of row e)
__device__ __forceinline__ void tile_store_f4(char* tile, int e, int lane, float4 t) {
    int ks  = lane >> 2;
    int reg = (e >> 3) + ((lane >> 1) & 1) * 2;
    int lp0 = (e & 7) * 4 + (lane & 1) * 2;
    char* base = tile + ks * 528 + reg * 4;
    *(uint32_t*)(base + lp0 * 16)       = packh2(t.x, t.y);
    *(uint32_t*)(base + (lp0 + 1) * 16) = packh2(t.z, t.w);
}
// Tile store from pre-packed fp16 (u0 = cols 4L,4L+1; u1 = 4L+2,4L+3)
__device__ __forceinline__ void tile_store_h2(char* tile, int e, int lane, uint32_t u0, uint32_t u1) {
    int ks  = lane >> 2;
    int reg = (e >> 3) + ((lane >> 1) & 1) * 2;
    int lp0 = (e & 7) * 4 + (lane & 1) * 2;
    char* base = tile + ks * 528 + reg * 4;
    *(uint32_t*)(base + lp0 * 16)       = u0;
    *(uint32_t*)(base + (lp0 + 1) * 16) = u1;
}

// m16 x n128 x k128 fp16 mainloop: 128 mma16.
__device__ __forceinline__ void mma_mainloop_h(float4 acc[16], const char* tile,
                                               const uint2* Wb, int lane) {
    #pragma unroll
    for (int nb = 0; nb < 16; nb++) acc[nb] = make_float4(0.f, 0.f, 0.f, 0.f);
    #pragma unroll
    for (int ks = 0; ks < 8; ks++) {
        uint4 af = *(const uint4*)(tile + ks * 528 + lane * 16);
        const uint2* wrow = Wb + ks * 512 + lane;
        #pragma unroll
        for (int nb = 0; nb < 16; nb++) {
            uint2 Bv = wrow[nb * 32];
            mma16(acc[nb], af, Bv);
        }
    }
}

__device__ __forceinline__ void redv2(float* p, float a, float b) {
    asm volatile("red.global.add.v2.f32 [%0], {%1, %2};" :: "l"(p), "f"(a), "f"(b) : "memory");
}

// ======================= AB GEMM: A = X@Wa + ba (fp32) ; B = X@Wb + bb (fp16) =======================
// H16IN: X is packed-fp16, already relu'd (inter-layer). Else fp32 raw input.
template <bool H16IN>
__global__ void __launch_bounds__(TPB, 1)
ab_mma_kernel(const void* __restrict__ Xv, const float* __restrict__ Wa,
              const float* __restrict__ Wbm, const float* __restrict__ ba,
              const float* __restrict__ bb, float* __restrict__ Aout,
              uint32_t* __restrict__ Bout, int nrows)
{
    extern __shared__ char sm[];
    uint2* bankA = (uint2*)sm;
    uint2* bankB = (uint2*)(sm + 32768);
    const int tid = threadIdx.x, wid = tid >> 5, lane = tid & 31;
    char* tile = sm + 65536 + wid * TILE_B;

    stage_w_h2(bankA, Wa);
    stage_w_h2(bankB, Wbm);
    __syncthreads();

    const int gwarp  = blockIdx.x * 16 + wid;
    const int nwarps = gridDim.x * 16;
    const int ntasks = (nrows + 15) / 16;

    for (int task = gwarp; task < ntasks; task += nwarps) {
        const int r0 = task * 16;

        #pragma unroll 4
        for (int e = 0; e < 16; e++) {
            int r = r0 + e;
            if (H16IN) {
                uint2 v = make_uint2(0u, 0u);
                if (r < nrows) v = ((const uint2*)Xv)[r * 32 + lane];
                tile_store_h2(tile, e, lane, v.x, v.y);
            } else {
                float4 t = make_float4(0.f, 0.f, 0.f, 0.f);
                if (r < nrows) t = ((const float4*)Xv)[r * 32 + lane];
                tile_store_f4(tile, e, lane, t);
            }
        }
        __syncwarp();

        const int i0 = r0 + (lane >> 2);
        const int i1 = i0 + 8;
        float4 acc[16];

        // ---- A output (fp32) ----
        mma_mainloop_h(acc, tile, bankA, lane);
        #pragma unroll
        for (int nb = 0; nb < 16; nb++) {
            int c = 2 * (lane & 3) + nb * 8;
            float b0 = __ldg(ba + c), b1 = __ldg(ba + c + 1);
            if (i0 < nrows)
                *(float2*)(Aout + (size_t)i0 * 128 + c) = make_float2(acc[nb].x + b0, acc[nb].y + b1);
            if (i1 < nrows)
                *(float2*)(Aout + (size_t)i1 * 128 + c) = make_float2(acc[nb].z + b0, acc[nb].w + b1);
        }

        // ---- B output (fp16 packed) ----
        mma_mainloop_h(acc, tile, bankB, lane);
        #pragma unroll
        for (int nb = 0; nb < 16; nb++) {
            int c = 2 * (lane & 3) + nb * 8;
            float b0 = __ldg(bb + c), b1 = __ldg(bb + c + 1);
            if (i0 < nrows)
                Bout[(size_t)i0 * 64 + (c >> 1)] = packh2(acc[nb].x + b0, acc[nb].y + b1);
            if (i1 < nrows)
                Bout[(size_t)i1 * 64 + (c >> 1)] = packh2(acc[nb].z + b0, acc[nb].w + b1);
        }
        __syncwarp();
    }
}

// ======================= msg GEMM: out = T @ w2 + (deg+1)*b2 =======================
// POOL: relu + mean-pool atomics into pool[batch]; else relu + pack fp16 into agg16.
template <bool POOL>
__global__ void __launch_bounds__(TPB, 1)
msg_mma_kernel(const uint32_t* __restrict__ Th, const float* __restrict__ W2,
               const float* __restrict__ b2, const int* __restrict__ deg,
               const int* __restrict__ batch, uint32_t* __restrict__ agg16,
               float* __restrict__ pool, int nrows)
{
    extern __shared__ char sm[];
    uint2* bankW = (uint2*)sm;
    const int tid = threadIdx.x, wid = tid >> 5, lane = tid & 31;
    char* tile = sm + 32768 + wid * TILE_B;

    stage_w_h2(bankW, W2);
    __syncthreads();

    const int gwarp  = blockIdx.x * 16 + wid;
    const int nwarps = gridDim.x * 16;
    const int ntasks = (nrows + 15) / 16;

    for (int task = gwarp; task < ntasks; task += nwarps) {
        const int r0 = task * 16;

        #pragma unroll 4
        for (int e = 0; e < 16; e++) {
            int r = r0 + e;
            uint2 v = make_uint2(0u, 0u);
            if (r < nrows) v = ((const uint2*)Th)[r * 32 + lane];
            tile_store_h2(tile, e, lane, v.x, v.y);
        }
        __syncwarp();

        float4 acc[16];
        mma_mainloop_h(acc, tile, bankW, lane);
        __syncwarp();

        int i0 = r0 + (lane >> 2);
        int i1 = i0 + 8;
        float s0 = 0.f, s1 = 0.f;
        int g0 = 0, g1 = 0;
        if (i0 < nrows) { s0 = (float)(__ldg(deg + i0) + 1); if (POOL) g0 = __ldg(batch + i0); }
        if (i1 < nrows) { s1 = (float)(__ldg(deg + i1) + 1); if (POOL) g1 = __ldg(batch + i1); }
        #pragma unroll
        for (int nb = 0; nb < 16; nb++) {
            int c = 2 * (lane & 3) + nb * 8;
            float q0 = __ldg(b2 + c), q1 = __ldg(b2 + c + 1);
            float v0x = fmaxf(acc[nb].x + s0 * q0, 0.f), v0y = fmaxf(acc[nb].y + s0 * q1, 0.f);
            float v1x = fmaxf(acc[nb].z + s1 * q0, 0.f), v1y = fmaxf(acc[nb].w + s1 * q1, 0.f);
            if (POOL) {
                if (i0 < nrows) redv2(pool + (size_t)g0 * 128 + c, v0x, v0y);
                if (i1 < nrows) redv2(pool + (size_t)g1 * 128 + c, v1x, v1y);
            } else {
                if (i0 < nrows) agg16[(size_t)i0 * 64 + (c >> 1)] = packh2(v0x, v0y);
                if (i1 < nrows) agg16[(size_t)i1 * 64 + (c >> 1)] = packh2(v1x, v1y);
            }
        }
    }
}

// ======================= accum (high occupancy, no smem) =======================
// T[n] = relu(A[n]+B[n]) + sum_{e in CSR[n]} relu(A[n]+B[ssrc[e]]) ; T packed fp16.
__global__ void __launch_bounds__(512)
accum_kernel(const float* __restrict__ A, const uint32_t* __restrict__ Bh,
             const int* __restrict__ ssrc, const int* __restrict__ start,
             uint32_t* __restrict__ Th, int n)
{
    const int gw   = (blockIdx.x * blockDim.x + threadIdx.x) >> 5;
    const int lane = threadIdx.x & 31;
    const int nw   = (gridDim.x * blockDim.x) >> 5;

    for (int node = gw; node < n; node += nw) {
        float4 a = ((const float4*)(A + (size_t)node * 128))[lane];
        uint2 vs = ((const uint2*)Bh)[node * 32 + lane];
        float2 s0 = unpackh2(vs.x), s1 = unpackh2(vs.y);
        float4 acc = relu4(make_float4(a.x + s0.x, a.y + s0.y, a.z + s1.x, a.w + s1.y)); // self loop

        int e  = __ldg(start + node);
        int e1 = __ldg(start + node + 1);
        for (; e + 4 <= e1; e += 4) {
            int j0 = __ldg(ssrc + e),     j1 = __ldg(ssrc + e + 1);
            int j2 = __ldg(ssrc + e + 2), j3 = __ldg(ssrc + e + 3);
            uint2 v0 = ((const uint2*)Bh)[j0 * 32 + lane];
            uint2 v1 = ((const uint2*)Bh)[j1 * 32 + lane];
            uint2 v2 = ((const uint2*)Bh)[j2 * 32 + lane];
            uint2 v3 = ((const uint2*)Bh)[j3 * 32 + lane];
            float2 p0a = unpackh2(v0.x), p0b = unpackh2(v0.y);
            float2 p1a = unpackh2(v1.x), p1b = unpackh2(v1.y);
            float2 p2a = unpackh2(v2.x), p2b = unpackh2(v2.y);
            float2 p3a = unpackh2(v3.x), p3b = unpackh2(v3.y);
            float4 t0 = relu4(make_float4(a.x + p0a.x, a.y + p0a.y, a.z + p0b.x, a.w + p0b.y));
            float4 t1 = relu4(make_float4(a.x + p1a.x, a.y + p1a.y, a.z + p1b.x, a.w + p1b.y));
            float4 t2 = relu4(make_float4(a.x + p2a.x, a.y + p2a.y, a.z + p2b.x, a.w + p2b.y));
            float4 t3 = relu4(make_float4(a.x + p3a.x, a.y + p3a.y, a.z + p3b.x, a.w + p3b.y));
            acc.x += t0.x + t1.x + t2.x + t3.x;
            acc.y += t0.y + t1.y + t2.y + t3.y;
            acc.z += t0.z + t1.z + t2.z + t3.z;
            acc.w += t0.w + t1.w + t2.w + t3.w;
        }
        for (; e < e1; e++) {
            int j = __ldg(ssrc + e);
            uint2 v = ((const uint2*)Bh)[j * 32 + lane];
            float2 pa = unpackh2(v.x), pb = unpackh2(v.y);
            float4 t = relu4(make_float4(a.x + pa.x, a.y + pa.y, a.z + pb.x, a.w + pb.y));
            acc.x += t.x; acc.y += t.y; acc.z += t.z; acc.w += t.w;
        }
        ((uint2*)Th)[node * 32 + lane] = make_uint2(packh2(acc.x, acc.y), packh2(acc.z, acc.w));
    }
}

// ======================= weight composition: ALL 6 outputs in one launch =======================
// blockIdx.x = k row (0..127), blockIdx.y = j (0..5): layer l = j>>1, half p = j&1
// Wc[j][k][m] = sum_n Wlin_l[k][n] * w1_l[p*128 + n][m]
__global__ void compose_all_kernel(const float* __restrict__ lw0, const float* __restrict__ lw1,
                                   const float* __restrict__ lw2, const float* __restrict__ w10,
                                   const float* __restrict__ w11, const float* __restrict__ w12,
                                   float* __restrict__ Wc)
{
    __shared__ float row[128];
    const int j = blockIdx.y, l = j >> 1, p = j & 1;
    const float* Wlin = (l == 0) ? lw0 : (l == 1) ? lw1 : lw2;
    const float* w1p  = ((l == 0) ? w10 : (l == 1) ? w11 : w12) + p * 128 * 128;
    const int k = blockIdx.x, m = threadIdx.x;
    row[m] = Wlin[k * 128 + m];
    __syncthreads();
    float s0 = 0.f, s1 = 0.f, s2 = 0.f, s3 = 0.f;
    #pragma unroll 8
    for (int n = 0; n < 128; n += 4) {
        s0 += row[n    ] * w1p[(n    ) * 128 + m];
        s1 += row[n + 1] * w1p[(n + 1) * 128 + m];
        s2 += row[n + 2] * w1p[(n + 2) * 128 + m];
        s3 += row[n + 3] * w1p[(n + 3) * 128 + m];
    }
    Wc[j * 16384 + k * 128 + m] = (s0 + s1) + (s2 + s3);
}

// All 6 composite biases in one launch. blockIdx.x = j (0..5).
__global__ void bias_all_kernel(const float* __restrict__ lb0, const float* __restrict__ lb1,
                                const float* __restrict__ lb2, const float* __restrict__ w10,
                                const float* __restrict__ w11, const float* __restrict__ w12,
                                const float* __restrict__ b10, const float* __restrict__ b11,
                                const float* __restrict__ b12, float* __restrict__ bc)
{
    const int j = blockIdx.x, l = j >> 1, p = j & 1;
    const float* lin_b = (l == 0) ? lb0 : (l == 1) ? lb1 : lb2;
    const float* w1p   = ((l == 0) ? w10 : (l == 1) ? w11 : w12) + p * 128 * 128;
    const float* b1    = (l == 0) ? b10 : (l == 1) ? b11 : b12;
    const int m = threadIdx.x;
    float s0 = (p == 0) ? b1[m] : 0.f;
    float s1 = 0.f, s2 = 0.f, s3 = 0.f;
    #pragma unroll 8
    for (int n = 0; n < 128; n += 4) {
        s0 += lin_b[n    ] * w1p[(n    ) * 128 + m];
        s1 += lin_b[n + 1] * w1p[(n + 1) * 128 + m];
        s2 += lin_b[n + 2] * w1p[(n + 2) * 128 + m];
        s3 += lin_b[n + 3] * w1p[(n + 3) * 128 + m];
    }
    bc[j * 128 + m] = (s0 + s1) + (s2 + s3);
}

// ======================= CSR / counts / final =======================
__global__ void degcnt_kernel(const int* __restrict__ dst, const int* __restrict__ batch,
                              int* __restrict__ deg, float* __restrict__ cnt, int E, int n)
{
    int i = blockIdx.x * blockDim.x + threadIdx.x;
    if (i < E) atomicAdd(&deg[dst[i]], 1);
    if (i < n) atomicAdd(&cnt[batch[i]], 1.f);
}

__global__ void scan_kernel(const int* __restrict__ deg, int* __restrict__ start,
                            int* __restrict__ cursor, int n)
{
    __shared__ int carry;
    __shared__ int wsum[32];
    const int tidx = threadIdx.x, lane = tidx & 31, wid = tidx >> 5;
    if (tidx == 0) carry = 0;
    __syncthreads();

    for (int base = 0; base < n; base += 1024) {
        int i = base + tidx;
        int v = (i < n) ? deg[i] : 0;
        int x = v;
        #pragma unroll
        for (int o = 1; o < 32; o <<= 1) {
            int y = __shfl_up_sync(0xffffffffu, x, o);
            if (lane >= o) x += y;
        }
        if (lane == 31) wsum[wid] = x;
        __syncthreads();
        if (wid == 0) {
            int w = wsum[lane];
            #pragma unroll
            for (int o = 1; o < 32; o <<= 1) {
                int y = __shfl_up_sync(0xffffffffu, w, o);
                if (lane >= o) w += y;
            }
            wsum[lane] = w;
        }
        __syncthreads();
        int excl = x - v + (wid > 0 ? wsum[wid - 1] : 0) + carry;
        if (i < n) { start[i] = excl; cursor[i] = excl; }
        int blocktot = wsum[31];
        __syncthreads();
        if (tidx == 0) carry += blocktot;
        __syncthreads();
    }
    if (tidx == 0) start[n] = carry;
}

__global__ void scatter_kernel(const int* __restrict__ src, const int* __restrict__ dst,
                               int* __restrict__ cursor, int* __restrict__ ssrc, int E)
{
    int i = blockIdx.x * blockDim.x + threadIdx.x;
    if (i < E) {
        int p = atomicAdd(&cursor[dst[i]], 1);
        ssrc[p] = src[i];
    }
}

__global__ void final_kernel(const float* __restrict__ pool, const float* __restrict__ cnt,
                             const float* __restrict__ W, const float* __restrict__ b,
                             float* __restrict__ out)
{
    __shared__ float p[128];
    int g = blockIdx.x;
    float c = fmaxf(cnt[g], 1.f);
    for (int j = threadIdx.x; j < 128; j += blockDim.x)
        p[j] = pool[(size_t)g * 128 + j] / c;
    __syncthreads();
    int o = threadIdx.x;
    float s = b[o];
    #pragma unroll 4
    for (int j = 0; j < 128; j++) s += p[j] * W[j * 64 + o];
    out[(size_t)g * 64 + o] = s;
}

// ======================= launch =======================
extern "C" void kernel_launch(void* const* d_in, const int* in_sizes, int n_in,
                              void* d_out, int out_size)
{
    const float* x     = (const float*)d_in[0];
    const int*   ei    = (const int*)  d_in[1];
    const int*   batch = (const int*)  d_in[3];
    const int N = in_sizes[0] / 128;
    const int E = in_sizes[1] / 2;
    const int* src = ei;
    const int* dst = ei + E;

    const float* lin_w[3] = { (const float*)d_in[4],  (const float*)d_in[10], (const float*)d_in[16] };
    const float* lin_b[3] = { (const float*)d_in[5],  (const float*)d_in[11], (const float*)d_in[17] };
    const float* w1[3]    = { (const float*)d_in[6],  (const float*)d_in[12], (const float*)d_in[18] };
    const float* b1[3]    = { (const float*)d_in[7],  (const float*)d_in[13], (const float*)d_in[19] };
    const float* w2[3]    = { (const float*)d_in[8],  (const float*)d_in[14], (const float*)d_in[20] };
    const float* b2[3]    = { (const float*)d_in[9],  (const float*)d_in[15], (const float*)d_in[21] };
    const float* out_w    = (const float*)d_in[22];
    const float* out_b    = (const float*)d_in[23];
    float* out = (float*)d_out;

    float *A_, *pool_, *cnt_, *Wc_, *bc_;
    uint32_t *Bh_, *Th_, *aggh_;
    int *deg_, *start_, *cursor_, *ssrc_;
    cudaGetSymbolAddress((void**)&A_,     g_A);
    cudaGetSymbolAddress((void**)&Bh_,    g_Bh);
    cudaGetSymbolAddress((void**)&Th_,    g_Th);
    cudaGetSymbolAddress((void**)&aggh_,  g_aggh);
    cudaGetSymbolAddress((void**)&pool_,  g_pool);
    cudaGetSymbolAddress((void**)&cnt_,   g_cnt);
    cudaGetSymbolAddress((void**)&deg_,   g_deg);
    cudaGetSymbolAddress((void**)&start_, g_start);
    cudaGetSymbolAddress((void**)&cursor_,g_cursor);
    cudaGetSymbolAddress((void**)&ssrc_,  g_ssrc);
    cudaGetSymbolAddress((void**)&Wc_,    g_Wc);
    cudaGetSymbolAddress((void**)&bc_,    g_bc);

    cudaFuncSetAttribute((const void*)ab_mma_kernel<false>,
                         cudaFuncAttributeMaxDynamicSharedMemorySize, AB_SMEM);
    cudaFuncSetAttribute((const void*)ab_mma_kernel<true>,
                         cudaFuncAttributeMaxDynamicSharedMemorySize, AB_SMEM);
    cudaFuncSetAttribute((const void*)msg_mma_kernel<false>,
                         cudaFuncAttributeMaxDynamicSharedMemorySize, MSG_SMEM);
    cudaFuncSetAttribute((const void*)msg_mma_kernel<true>,
                         cudaFuncAttributeMaxDynamicSharedMemorySize, MSG_SMEM);

    const int G = out_size / 64;

    // ---- prep: CSR by dst, counts, composite weights (8 launches total) ----
    cudaMemsetAsync(deg_,  0, (size_t)N * sizeof(int));
    cudaMemsetAsync(pool_, 0, (size_t)G * 128 * sizeof(float));
    cudaMemsetAsync(cnt_,  0, (size_t)G * sizeof(float));
    degcnt_kernel<<<(E + 255) / 256, 256>>>(dst, batch, deg_, cnt_, E, N);
    compose_all_kernel<<<dim3(128, 6), 128>>>(lin_w[0], lin_w[1], lin_w[2],
                                              w1[0], w1[1], w1[2], Wc_);
    bias_all_kernel<<<6, 128>>>(lin_b[0], lin_b[1], lin_b[2],
                                w1[0], w1[1], w1[2],
                                b1[0], b1[1], b1[2], bc_);
    scan_kernel<<<1, 1024>>>(deg_, start_, cursor_, N);
    scatter_kernel<<<(E + 255) / 256, 256>>>(src, dst, cursor_, ssrc_, E);

    for (int l = 0; l < 3; l++) {
        const float* Wa = Wc_ + (2 * l    ) * 16384;
        const float* Wb = Wc_ + (2 * l + 1) * 16384;
        const float* ba = bc_ + (2 * l    ) * 128;
        const float* bb = bc_ + (2 * l + 1) * 128;
        if (l == 0)
            ab_mma_kernel<false><<<NBLK, TPB, AB_SMEM>>>(x, Wa, Wb, ba, bb, A_, Bh_, N);
        else
            ab_mma_kernel<true ><<<NBLK, TPB, AB_SMEM>>>(aggh_, Wa, Wb, ba, bb, A_, Bh_, N);
        accum_kernel<<<296, 512>>>(A_, Bh_, ssrc_, start_, Th_, N);
        if (l < 2)
            msg_mma_kernel<false><<<NBLK, TPB, MSG_SMEM>>>(Th_, w2[l], b2[l], deg_, batch, aggh_, pool_, N);
        else
            msg_mma_kernel<true ><<<NBLK, TPB, MSG_SMEM>>>(Th_, w2[l], b2[l], deg_, batch, aggh_, pool_, N);
    }

    final_kernel<<<G, 64>>>(pool_, cnt_, out_w, out_b, out);
}